// round 6
// baseline (speedup 1.0000x reference)
#include <cuda_runtime.h>
#include <cuda_bf16.h>
#include <cstdint>

// ---------------------------------------------------------------------------
// GATEncoder: 3 layers of (GATConv + linear skip + ELU)
// N=50000, E=800000 (+N self loops), IN=128, H=4, C=64, HC=256
// Round 6: node_agg rewritten — online softmax (1 gather pass) + MLP-batched
//          aggregation. GEMM = mma.sync bf16-split fused dual GEMM (unchanged).
// ---------------------------------------------------------------------------

#define NNODES 50000
#define NEDGES 800000
#define ETOT   (NEDGES + NNODES)
#define HC     256

// ------------------------- static device scratch ---------------------------
__device__ float g_h   [(size_t)NNODES * HC];
__device__ float g_acc [(size_t)NNODES * HC];
__device__ float g_x   [(size_t)NNODES * HC];
__device__ float g_s   [(size_t)NNODES * 4];
__device__ float g_d   [(size_t)NNODES * 4];
__device__ int   g_deg [NNODES];
__device__ int   g_cur [NNODES];
__device__ int   g_rp  [NNODES + 1];
__device__ int   g_csr [ETOT];
// pre-transposed bf16-split fused weights: [512 rows, K cols] per layer
__device__ __nv_bfloat16 g_bh[3][131072];
__device__ __nv_bfloat16 g_bl[3][131072];

// ------------------------- helpers ----------------------------------------
__device__ __forceinline__ float lrelu(float v) { return v > 0.f ? v : 0.2f * v; }

__device__ __forceinline__ void mma16816(float* d, const uint32_t* a,
                                         uint32_t b0, uint32_t b1) {
    asm volatile(
        "mma.sync.aligned.m16n8k16.row.col.f32.bf16.bf16.f32 "
        "{%0,%1,%2,%3}, {%4,%5,%6,%7}, {%8,%9}, {%0,%1,%2,%3};"
        : "+f"(d[0]), "+f"(d[1]), "+f"(d[2]), "+f"(d[3])
        : "r"(a[0]), "r"(a[1]), "r"(a[2]), "r"(a[3]), "r"(b0), "r"(b1));
}

// ------------------------- weight preconvert -------------------------------
__global__ void conv_w_kernel(const float* __restrict__ W,
                              __nv_bfloat16* __restrict__ hi,
                              __nv_bfloat16* __restrict__ lo,
                              int K, int rowoff) {
    const int idx = blockIdx.x * blockDim.x + threadIdx.x;
    if (idx >= K * 256) return;
    const int k = idx / 256;
    const int n = idx % 256;
    const float v = W[idx];
    const __nv_bfloat16 h = __float2bfloat16(v);
    const float r = v - __bfloat162float(h);
    hi[(size_t)(rowoff + n) * K + k] = h;
    lo[(size_t)(rowoff + n) * K + k] = __float2bfloat16(r);
}

// ------------------------- fused dual GEMM (mma.sync bf16 split) -----------
#define SSTR 40

__global__ __launch_bounds__(256, 2)
void gemm_mma_kernel(const float* __restrict__ A,
                     const __nv_bfloat16* __restrict__ Bh,
                     const __nv_bfloat16* __restrict__ Bl,
                     float* __restrict__ Ch,
                     float* __restrict__ Cacc,
                     const float* __restrict__ bias1,
                     const float* __restrict__ bias2,
                     int M, int K) {
    __shared__ __nv_bfloat16 sAh[128 * SSTR];
    __shared__ __nv_bfloat16 sAl[128 * SSTR];
    __shared__ __nv_bfloat16 sBh[128 * SSTR];
    __shared__ __nv_bfloat16 sBl[128 * SSTR];

    const int tid = threadIdx.x;
    const int wid = tid >> 5;
    const int lane = tid & 31;
    const int qr = lane >> 2;
    const int qc = (lane & 3) * 2;
    const int warp_m = (wid >> 2) * 64;
    const int warp_n = (wid & 3) * 32;
    const int m0 = blockIdx.y * 128;
    const int n0 = blockIdx.x * 128;

    float d[4][4][4];
#pragma unroll
    for (int mt = 0; mt < 4; mt++)
#pragma unroll
        for (int nt = 0; nt < 4; nt++)
#pragma unroll
            for (int r = 0; r < 4; r++) d[mt][nt][r] = 0.f;

    const int nch = K >> 5;
    for (int ch = 0; ch < nch; ch++) {
        const int k0 = ch << 5;

#pragma unroll
        for (int i = 0; i < 2; i++) {
            const int s = tid + i * 256;
            const int r = s >> 2;
            const int c8 = (s & 3) * 8;
            float4 f0 = make_float4(0.f, 0.f, 0.f, 0.f);
            float4 f1 = make_float4(0.f, 0.f, 0.f, 0.f);
            if (m0 + r < M) {
                const float* ap = &A[(size_t)(m0 + r) * K + k0 + c8];
                f0 = *(const float4*)ap;
                f1 = *(const float4*)(ap + 4);
            }
            __nv_bfloat162 h0 = __floats2bfloat162_rn(f0.x, f0.y);
            __nv_bfloat162 h1 = __floats2bfloat162_rn(f0.z, f0.w);
            __nv_bfloat162 h2 = __floats2bfloat162_rn(f1.x, f1.y);
            __nv_bfloat162 h3 = __floats2bfloat162_rn(f1.z, f1.w);
            __nv_bfloat162 l0 = __floats2bfloat162_rn(f0.x - __low2float(h0), f0.y - __high2float(h0));
            __nv_bfloat162 l1 = __floats2bfloat162_rn(f0.z - __low2float(h1), f0.w - __high2float(h1));
            __nv_bfloat162 l2 = __floats2bfloat162_rn(f1.x - __low2float(h2), f1.y - __high2float(h2));
            __nv_bfloat162 l3 = __floats2bfloat162_rn(f1.z - __low2float(h3), f1.w - __high2float(h3));
            uint4 uh = make_uint4(*(uint32_t*)&h0, *(uint32_t*)&h1, *(uint32_t*)&h2, *(uint32_t*)&h3);
            uint4 ul = make_uint4(*(uint32_t*)&l0, *(uint32_t*)&l1, *(uint32_t*)&l2, *(uint32_t*)&l3);
            *(uint4*)&sAh[r * SSTR + c8] = uh;
            *(uint4*)&sAl[r * SSTR + c8] = ul;
        }
        {
            const int n = tid >> 1;
            const int kh = (tid & 1) * 16;
            const size_t goff = (size_t)(n0 + n) * K + k0 + kh;
            const uint4 vh0 = *(const uint4*)&Bh[goff];
            const uint4 vh1 = *(const uint4*)&Bh[goff + 8];
            const uint4 vl0 = *(const uint4*)&Bl[goff];
            const uint4 vl1 = *(const uint4*)&Bl[goff + 8];
            *(uint4*)&sBh[n * SSTR + kh] = vh0;
            *(uint4*)&sBh[n * SSTR + kh + 8] = vh1;
            *(uint4*)&sBl[n * SSTR + kh] = vl0;
            *(uint4*)&sBl[n * SSTR + kh + 8] = vl1;
        }
        __syncthreads();

#pragma unroll
        for (int ks = 0; ks < 2; ks++) {
            const int kk = ks * 16;
            uint32_t ah[4][4], al[4][4];
#pragma unroll
            for (int mt = 0; mt < 4; mt++) {
                const int r0 = warp_m + mt * 16 + qr;
                ah[mt][0] = *(const uint32_t*)&sAh[r0 * SSTR + kk + qc];
                ah[mt][1] = *(const uint32_t*)&sAh[(r0 + 8) * SSTR + kk + qc];
                ah[mt][2] = *(const uint32_t*)&sAh[r0 * SSTR + kk + 8 + qc];
                ah[mt][3] = *(const uint32_t*)&sAh[(r0 + 8) * SSTR + kk + 8 + qc];
                al[mt][0] = *(const uint32_t*)&sAl[r0 * SSTR + kk + qc];
                al[mt][1] = *(const uint32_t*)&sAl[(r0 + 8) * SSTR + kk + qc];
                al[mt][2] = *(const uint32_t*)&sAl[r0 * SSTR + kk + 8 + qc];
                al[mt][3] = *(const uint32_t*)&sAl[(r0 + 8) * SSTR + kk + 8 + qc];
            }
#pragma unroll
            for (int nt = 0; nt < 4; nt++) {
                const int nr = warp_n + nt * 8 + qr;
                const uint32_t bh0 = *(const uint32_t*)&sBh[nr * SSTR + kk + qc];
                const uint32_t bh1 = *(const uint32_t*)&sBh[nr * SSTR + kk + 8 + qc];
                const uint32_t bl0 = *(const uint32_t*)&sBl[nr * SSTR + kk + qc];
                const uint32_t bl1 = *(const uint32_t*)&sBl[nr * SSTR + kk + 8 + qc];
#pragma unroll
                for (int mt = 0; mt < 4; mt++) {
                    mma16816(d[mt][nt], ah[mt], bh0, bh1);
                    mma16816(d[mt][nt], ah[mt], bl0, bl1);
                    mma16816(d[mt][nt], al[mt], bh0, bh1);
                }
            }
        }
        __syncthreads();
    }

#pragma unroll
    for (int nt = 0; nt < 4; nt++) {
        const int gcol = n0 + warp_n + nt * 8 + qc;
        float* out;
        int col;
        float bv0 = 0.f, bv1 = 0.f;
        if (gcol < 256) {
            out = Ch;  col = gcol;
        } else {
            out = Cacc;  col = gcol - 256;
            bv0 = bias1[col] + bias2[col];
            bv1 = bias1[col + 1] + bias2[col + 1];
        }
#pragma unroll
        for (int mt = 0; mt < 4; mt++) {
            const int r0 = m0 + warp_m + mt * 16 + qr;
            if (r0 < M) {
                float2 v = make_float2(d[mt][nt][0] + bv0, d[mt][nt][1] + bv1);
                *(float2*)&out[(size_t)r0 * HC + col] = v;
            }
            if (r0 + 8 < M) {
                float2 v = make_float2(d[mt][nt][2] + bv0, d[mt][nt][3] + bv1);
                *(float2*)&out[(size_t)(r0 + 8) * HC + col] = v;
            }
        }
    }
}

// ------------------------- CSR build ---------------------------------------
__global__ void hist_kernel(const int* __restrict__ ei, int* __restrict__ deg,
                            int nE, int nTot) {
    const int e = blockIdx.x * blockDim.x + threadIdx.x;
    if (e >= nTot) return;
    const int d = (e < nE) ? ei[nE + e] : (e - nE);
    atomicAdd(&deg[d], 1);
}

__global__ __launch_bounds__(1024)
void scan_kernel(const int* __restrict__ deg, int* __restrict__ rp,
                 int* __restrict__ cur, int n) {
    __shared__ int part[1024];
    const int t = threadIdx.x;
    const int CH = (n + 1023) / 1024;
    const int start = t * CH;
    int s = 0;
    for (int i = 0; i < CH; i++) {
        const int idx = start + i;
        if (idx < n) s += deg[idx];
    }
    part[t] = s;
    __syncthreads();
    for (int off = 1; off < 1024; off <<= 1) {
        int v = (t >= off) ? part[t - off] : 0;
        __syncthreads();
        part[t] += v;
        __syncthreads();
    }
    int base = (t == 0) ? 0 : part[t - 1];
    for (int i = 0; i < CH; i++) {
        const int idx = start + i;
        if (idx < n) {
            rp[idx] = base;
            cur[idx] = base;
            base += deg[idx];
        }
    }
    if (t == 1023) rp[n] = part[1023];
}

__global__ void scatter_kernel(const int* __restrict__ ei, int* __restrict__ cur,
                               int* __restrict__ csr, int nE, int nTot) {
    const int e = blockIdx.x * blockDim.x + threadIdx.x;
    if (e >= nTot) return;
    int s, d;
    if (e < nE) { s = ei[e]; d = ei[nE + e]; }
    else        { s = d = e - nE; }
    const int pos = atomicAdd(&cur[d], 1);
    csr[pos] = s;
}

// ------------------------- s/d per node ------------------------------------
__global__ void compute_sd_kernel(const float* __restrict__ gh,
                                  const float* __restrict__ a_src,
                                  const float* __restrict__ a_dst,
                                  float* __restrict__ gs, float* __restrict__ gd,
                                  int n_nodes) {
    const int warp = (blockIdx.x * blockDim.x + threadIdx.x) >> 5;
    const int lane = threadIdx.x & 31;
    if (warp >= n_nodes) return;
    const float* hr = gh + (size_t)warp * HC;
#pragma unroll
    for (int h = 0; h < 4; h++) {
        const float h1 = hr[h * 64 + lane];
        const float h2 = hr[h * 64 + 32 + lane];
        float s = h1 * a_src[h * 64 + lane] + h2 * a_src[h * 64 + 32 + lane];
        float d = h1 * a_dst[h * 64 + lane] + h2 * a_dst[h * 64 + 32 + lane];
#pragma unroll
        for (int off = 16; off > 0; off >>= 1) {
            s += __shfl_down_sync(0xFFFFFFFFu, s, off);
            d += __shfl_down_sync(0xFFFFFFFFu, d, off);
        }
        if (lane == 0) {
            gs[warp * 4 + h] = s;
            gd[warp * 4 + h] = d;
        }
    }
}

// ------------------------- fused softmax + aggregate + skip + ELU ----------
// one warp per dst node. Pass A: ONLINE softmax (single gather) -> (m, den).
// Pass B: batched staging (32 edges) -> MLP-friendly h[src] accumulate loop.
__global__ __launch_bounds__(256)
void node_agg_kernel(const int* __restrict__ rp, const int* __restrict__ csr,
                     const float* __restrict__ gs, const float* __restrict__ gd,
                     const float* __restrict__ gh, const float* __restrict__ gskip,
                     float* __restrict__ xout, int nN) {
    __shared__ float4 salpha[8][32];

    const int v = (blockIdx.x * blockDim.x + threadIdx.x) >> 5;
    const int lane = threadIdx.x & 31;
    const int wib = (threadIdx.x >> 5) & 7;
    if (v >= nN) return;

    const int b = rp[v];
    const int e = rp[v + 1];
    const float4 dv = ((const float4*)gd)[v];

    // ---- pass A: online (max, denom) per head, single gather pass ----
    float m0 = -1e30f, m1 = -1e30f, m2 = -1e30f, m3 = -1e30f;
    float n0 = 0.f, n1 = 0.f, n2 = 0.f, n3 = 0.f;
    for (int i = b + lane; i < e; i += 32) {
        const float4 sv = ((const float4*)gs)[csr[i]];
        const float e0 = lrelu(sv.x + dv.x);
        const float e1 = lrelu(sv.y + dv.y);
        const float e2 = lrelu(sv.z + dv.z);
        const float e3 = lrelu(sv.w + dv.w);
        const float M0 = fmaxf(m0, e0), M1 = fmaxf(m1, e1);
        const float M2 = fmaxf(m2, e2), M3 = fmaxf(m3, e3);
        n0 = n0 * expf(m0 - M0) + expf(e0 - M0);
        n1 = n1 * expf(m1 - M1) + expf(e1 - M1);
        n2 = n2 * expf(m2 - M2) + expf(e2 - M2);
        n3 = n3 * expf(m3 - M3) + expf(e3 - M3);
        m0 = M0; m1 = M1; m2 = M2; m3 = M3;
    }
#pragma unroll
    for (int off = 16; off > 0; off >>= 1) {
        const float om0 = __shfl_xor_sync(0xFFFFFFFFu, m0, off);
        const float om1 = __shfl_xor_sync(0xFFFFFFFFu, m1, off);
        const float om2 = __shfl_xor_sync(0xFFFFFFFFu, m2, off);
        const float om3 = __shfl_xor_sync(0xFFFFFFFFu, m3, off);
        const float on0 = __shfl_xor_sync(0xFFFFFFFFu, n0, off);
        const float on1 = __shfl_xor_sync(0xFFFFFFFFu, n1, off);
        const float on2 = __shfl_xor_sync(0xFFFFFFFFu, n2, off);
        const float on3 = __shfl_xor_sync(0xFFFFFFFFu, n3, off);
        const float M0 = fmaxf(m0, om0), M1 = fmaxf(m1, om1);
        const float M2 = fmaxf(m2, om2), M3 = fmaxf(m3, om3);
        n0 = n0 * expf(m0 - M0) + on0 * expf(om0 - M0);
        n1 = n1 * expf(m1 - M1) + on1 * expf(om1 - M1);
        n2 = n2 * expf(m2 - M2) + on2 * expf(om2 - M2);
        n3 = n3 * expf(m3 - M3) + on3 * expf(om3 - M3);
        m0 = M0; m1 = M1; m2 = M2; m3 = M3;
    }
    const float i0 = 1.f / (n0 + 1e-16f);
    const float i1 = 1.f / (n1 + 1e-16f);
    const float i2 = 1.f / (n2 + 1e-16f);
    const float i3 = 1.f / (n3 + 1e-16f);

    // ---- pass B: batched aggregate; lane owns channels [lane*8, lane*8+8) --
    const int h = lane >> 3;
    float4 a0 = make_float4(0.f, 0.f, 0.f, 0.f);
    float4 a1 = make_float4(0.f, 0.f, 0.f, 0.f);

    for (int base = b; base < e; base += 32) {
        const int nb = min(32, e - base);
        int sidx = 0;
        if (lane < nb) {
            sidx = csr[base + lane];
            const float4 sv = ((const float4*)gs)[sidx];
            float4 al;
            al.x = expf(lrelu(sv.x + dv.x) - m0) * i0;
            al.y = expf(lrelu(sv.y + dv.y) - m1) * i1;
            al.z = expf(lrelu(sv.z + dv.z) - m2) * i2;
            al.w = expf(lrelu(sv.w + dv.w) - m3) * i3;
            salpha[wib][lane] = al;
        }
        __syncwarp();
#pragma unroll 4
        for (int j = 0; j < nb; j++) {
            const int s = __shfl_sync(0xFFFFFFFFu, sidx, j);
            const float a = ((const float*)&salpha[wib][j])[h];
            const float4* hp = (const float4*)(gh + (size_t)s * HC) + lane * 2;
            const float4 v0 = hp[0];
            const float4 v1 = hp[1];
            a0.x = fmaf(v0.x, a, a0.x);  a0.y = fmaf(v0.y, a, a0.y);
            a0.z = fmaf(v0.z, a, a0.z);  a0.w = fmaf(v0.w, a, a0.w);
            a1.x = fmaf(v1.x, a, a1.x);  a1.y = fmaf(v1.y, a, a1.y);
            a1.z = fmaf(v1.z, a, a1.z);  a1.w = fmaf(v1.w, a, a1.w);
        }
        __syncwarp();
    }

    // ---- skip + ELU + store ----
    const float4* sp = (const float4*)(gskip + (size_t)v * HC) + lane * 2;
    const float4 s0 = sp[0];
    const float4 s1 = sp[1];
    float4 o0, o1;
    o0.x = a0.x + s0.x;  o0.y = a0.y + s0.y;  o0.z = a0.z + s0.z;  o0.w = a0.w + s0.w;
    o1.x = a1.x + s1.x;  o1.y = a1.y + s1.y;  o1.z = a1.z + s1.z;  o1.w = a1.w + s1.w;
    o0.x = o0.x > 0.f ? o0.x : expm1f(o0.x);
    o0.y = o0.y > 0.f ? o0.y : expm1f(o0.y);
    o0.z = o0.z > 0.f ? o0.z : expm1f(o0.z);
    o0.w = o0.w > 0.f ? o0.w : expm1f(o0.w);
    o1.x = o1.x > 0.f ? o1.x : expm1f(o1.x);
    o1.y = o1.y > 0.f ? o1.y : expm1f(o1.y);
    o1.z = o1.z > 0.f ? o1.z : expm1f(o1.z);
    o1.w = o1.w > 0.f ? o1.w : expm1f(o1.w);
    float4* op = (float4*)(xout + (size_t)v * HC) + lane * 2;
    op[0] = o0;
    op[1] = o1;
}

// ---------------------------------------------------------------------------
extern "C" void kernel_launch(void* const* d_in, const int* in_sizes, int n_in,
                              void* d_out, int out_size) {
    const float* x0 = (const float*)d_in[0];
    const int* ei = (const int*)d_in[1];
    const int nE = in_sizes[1] / 2;
    const int nN = NNODES;
    const int nTot = nE + nN;

    const float* W[3]    = {(const float*)d_in[2],  (const float*)d_in[8],  (const float*)d_in[14]};
    const float* ASRC[3] = {(const float*)d_in[3],  (const float*)d_in[9],  (const float*)d_in[15]};
    const float* ADST[3] = {(const float*)d_in[4],  (const float*)d_in[10], (const float*)d_in[16]};
    const float* BB[3]   = {(const float*)d_in[5],  (const float*)d_in[11], (const float*)d_in[17]};
    const float* SW[3]   = {(const float*)d_in[6],  (const float*)d_in[12], (const float*)d_in[18]};
    const float* SB[3]   = {(const float*)d_in[7],  (const float*)d_in[13], (const float*)d_in[19]};
    const int FIN[3] = {128, HC, HC};

    float *ph, *pacc, *px, *ps, *pd;
    int *pdeg, *pcur, *prp, *pcsr;
    __nv_bfloat16 *pbh, *pbl;
    cudaGetSymbolAddress((void**)&ph,   g_h);
    cudaGetSymbolAddress((void**)&pacc, g_acc);
    cudaGetSymbolAddress((void**)&px,   g_x);
    cudaGetSymbolAddress((void**)&ps,   g_s);
    cudaGetSymbolAddress((void**)&pd,   g_d);
    cudaGetSymbolAddress((void**)&pdeg, g_deg);
    cudaGetSymbolAddress((void**)&pcur, g_cur);
    cudaGetSymbolAddress((void**)&prp,  g_rp);
    cudaGetSymbolAddress((void**)&pcsr, g_csr);
    cudaGetSymbolAddress((void**)&pbh,  g_bh);
    cudaGetSymbolAddress((void**)&pbl,  g_bl);

    // ---- weight preconvert: fused [512,K] bf16 hi/lo per layer ----
    for (int l = 0; l < 3; l++) {
        const int K = FIN[l];
        const int nb = (K * 256 + 255) / 256;
        __nv_bfloat16* bh = pbh + (size_t)l * 131072;
        __nv_bfloat16* bl = pbl + (size_t)l * 131072;
        conv_w_kernel<<<nb, 256>>>(W[l],  bh, bl, K, 0);
        conv_w_kernel<<<nb, 256>>>(SW[l], bh, bl, K, 256);
    }

    // ---- CSR build (once; reused by all 3 layers) ----
    cudaMemsetAsync(pdeg, 0, NNODES * sizeof(int));
    const int eBlocks = (nTot + 255) / 256;
    hist_kernel<<<eBlocks, 256>>>(ei, pdeg, nE, nTot);
    scan_kernel<<<1, 1024>>>(pdeg, prp, pcur, nN);
    scatter_kernel<<<eBlocks, 256>>>(ei, pcur, pcsr, nE, nTot);

    const dim3 gemmGrid(4, (nN + 127) / 128);
    const int sdBlocks  = (nN * 32 + 255) / 256;
    const int aggBlocks = (nN * 32 + 255) / 256;

    const float* xin = x0;
    for (int l = 0; l < 3; l++) {
        const int K = FIN[l];
        __nv_bfloat16* bh = pbh + (size_t)l * 131072;
        __nv_bfloat16* bl = pbl + (size_t)l * 131072;
        gemm_mma_kernel<<<gemmGrid, 256>>>(xin, bh, bl, ph, pacc,
                                           BB[l], SB[l], nN, K);
        compute_sd_kernel<<<sdBlocks, 256>>>(ph, ASRC[l], ADST[l], ps, pd, nN);
        float* xout = (l == 2) ? (float*)d_out : px;
        node_agg_kernel<<<aggBlocks, 256>>>(prp, pcsr, ps, pd, ph, pacc, xout, nN);
        xin = px;
    }
}

// round 8
// speedup vs baseline: 1.0414x; 1.0414x over previous
#include <cuda_runtime.h>
#include <cuda_bf16.h>
#include <cstdint>

// ---------------------------------------------------------------------------
// GATEncoder: 3 layers of (GATConv + linear skip + ELU)
// N=50000, E=800000 (+N self loops), IN=128, H=4, C=64, HC=256
// Round 8: fix round-7 NaN (smem tiles half-loaded: one uint4 stored where
//          two were needed). A pre-split bf16 hi/lo in global; fused prep.
// ---------------------------------------------------------------------------

#define NNODES 50000
#define NEDGES 800000
#define ETOT   (NEDGES + NNODES)
#define HC     256

// ------------------------- static device scratch ---------------------------
__device__ float g_h   [(size_t)NNODES * HC];
__device__ float g_acc [(size_t)NNODES * HC];
__device__ float g_x   [(size_t)NNODES * HC];
__device__ float g_s   [(size_t)NNODES * 4];
__device__ float g_d   [(size_t)NNODES * 4];
__device__ int   g_deg [NNODES];
__device__ int   g_cur [NNODES];
__device__ int   g_rp  [NNODES + 1];
__device__ int   g_csr [ETOT];
// bf16 hi/lo split of the current layer's GEMM input A: [N, K<=256]
__device__ __nv_bfloat16 g_ah[(size_t)NNODES * HC];
__device__ __nv_bfloat16 g_al[(size_t)NNODES * HC];
// pre-transposed bf16-split fused weights: [512 rows, K cols] per layer
__device__ __nv_bfloat16 g_bh[3][131072];
__device__ __nv_bfloat16 g_bl[3][131072];

// ------------------------- helpers ----------------------------------------
__device__ __forceinline__ float lrelu(float v) { return v > 0.f ? v : 0.2f * v; }

__device__ __forceinline__ void mma16816(float* d, const uint32_t* a,
                                         uint32_t b0, uint32_t b1) {
    asm volatile(
        "mma.sync.aligned.m16n8k16.row.col.f32.bf16.bf16.f32 "
        "{%0,%1,%2,%3}, {%4,%5,%6,%7}, {%8,%9}, {%0,%1,%2,%3};"
        : "+f"(d[0]), "+f"(d[1]), "+f"(d[2]), "+f"(d[3])
        : "r"(a[0]), "r"(a[1]), "r"(a[2]), "r"(a[3]), "r"(b0), "r"(b1));
}

// ------------------------- prep: all weight splits + deg zero --------------
__global__ void prep_kernel(const float* __restrict__ W1, const float* __restrict__ SW1,
                            const float* __restrict__ W2, const float* __restrict__ SW2,
                            const float* __restrict__ W3, const float* __restrict__ SW3,
                            __nv_bfloat16* __restrict__ bh,
                            __nv_bfloat16* __restrict__ bl,
                            int* __restrict__ deg) {
    const int idx = blockIdx.x * blockDim.x + threadIdx.x;
    if (idx < NNODES) deg[idx] = 0;
    if (idx >= 327680) return;
    int l, which, mi, K;
    const float* src;
    if (idx < 65536)       { l = 0; K = 128; const int r = idx;          which = r >> 15; mi = r & 32767; src = which ? SW1 : W1; }
    else if (idx < 196608) { l = 1; K = 256; const int r = idx - 65536;  which = r >> 16; mi = r & 65535; src = which ? SW2 : W2; }
    else                   { l = 2; K = 256; const int r = idx - 196608; which = r >> 16; mi = r & 65535; src = which ? SW3 : W3; }
    const int k = mi >> 8;
    const int n = mi & 255;
    const float v = src[mi];
    const __nv_bfloat16 h = __float2bfloat16(v);
    const size_t off = (size_t)l * 131072 + (size_t)(which * 256 + n) * K + k;
    bh[off] = h;
    bl[off] = __float2bfloat16(v - __bfloat162float(h));
}

// ------------------------- conv_a: fp32 -> bf16 hi/lo (layer-1 input) ------
__global__ void conv_a_kernel(const float* __restrict__ X,
                              __nv_bfloat16* __restrict__ ah,
                              __nv_bfloat16* __restrict__ al, int total) {
    const int idx = blockIdx.x * blockDim.x + threadIdx.x;
    if (idx >= total) return;
    const float v = X[idx];
    const __nv_bfloat16 h = __float2bfloat16(v);
    ah[idx] = h;
    al[idx] = __float2bfloat16(v - __bfloat162float(h));
}

// ------------------------- fused dual GEMM (mma.sync bf16 split) -----------
// [Ch | Cacc][M,256|256] = A[M,K] @ [W | SW]^T, bias on the acc half.
// A pre-split bf16 hi/lo. CTA 128x128 of fused 512; 8 warps 64x32; BK=32.
#define SSTR 40

__global__ __launch_bounds__(256, 2)
void gemm_mma_kernel(const __nv_bfloat16* __restrict__ Ah,
                     const __nv_bfloat16* __restrict__ Al,
                     const __nv_bfloat16* __restrict__ Bh,
                     const __nv_bfloat16* __restrict__ Bl,
                     float* __restrict__ Ch,
                     float* __restrict__ Cacc,
                     const float* __restrict__ bias1,
                     const float* __restrict__ bias2,
                     int M, int K) {
    __shared__ __nv_bfloat16 sAh[128 * SSTR];
    __shared__ __nv_bfloat16 sAl[128 * SSTR];
    __shared__ __nv_bfloat16 sBh[128 * SSTR];
    __shared__ __nv_bfloat16 sBl[128 * SSTR];

    const int tid = threadIdx.x;
    const int wid = tid >> 5;
    const int lane = tid & 31;
    const int qr = lane >> 2;
    const int qc = (lane & 3) * 2;
    const int warp_m = (wid >> 2) * 64;
    const int warp_n = (wid & 3) * 32;
    const int m0 = blockIdx.y * 128;
    const int n0 = blockIdx.x * 128;

    float d[4][4][4];
#pragma unroll
    for (int mt = 0; mt < 4; mt++)
#pragma unroll
        for (int nt = 0; nt < 4; nt++)
#pragma unroll
            for (int r = 0; r < 4; r++) d[mt][nt][r] = 0.f;

    const int ar = tid >> 1;             // A row 0..127
    const int akh = (tid & 1) * 16;      // A col half: 16 bf16 via 2 uint4
    const int bn = tid >> 1;
    const int bkh = (tid & 1) * 16;

    const int nch = K >> 5;
    for (int ch = 0; ch < nch; ch++) {
        const int k0 = ch << 5;

        // ---- A tile 128x32 bf16 hi/lo (2 uint4 per thread per buf) ----
        {
            uint4 vh0 = make_uint4(0u, 0u, 0u, 0u), vh1 = vh0;
            uint4 vl0 = vh0, vl1 = vh0;
            if (m0 + ar < M) {
                const size_t off = (size_t)(m0 + ar) * K + k0 + akh;
                vh0 = *(const uint4*)&Ah[off];
                vh1 = *(const uint4*)&Ah[off + 8];
                vl0 = *(const uint4*)&Al[off];
                vl1 = *(const uint4*)&Al[off + 8];
            }
            *(uint4*)&sAh[ar * SSTR + akh]     = vh0;
            *(uint4*)&sAh[ar * SSTR + akh + 8] = vh1;
            *(uint4*)&sAl[ar * SSTR + akh]     = vl0;
            *(uint4*)&sAl[ar * SSTR + akh + 8] = vl1;
        }
        // ---- B tile 128(n)x32(k) bf16 hi/lo ----
        {
            const size_t goff = (size_t)(n0 + bn) * K + k0 + bkh;
            const uint4 wh0 = *(const uint4*)&Bh[goff];
            const uint4 wh1 = *(const uint4*)&Bh[goff + 8];
            const uint4 wl0 = *(const uint4*)&Bl[goff];
            const uint4 wl1 = *(const uint4*)&Bl[goff + 8];
            *(uint4*)&sBh[bn * SSTR + bkh]     = wh0;
            *(uint4*)&sBh[bn * SSTR + bkh + 8] = wh1;
            *(uint4*)&sBl[bn * SSTR + bkh]     = wl0;
            *(uint4*)&sBl[bn * SSTR + bkh + 8] = wl1;
        }
        __syncthreads();

#pragma unroll
        for (int ks = 0; ks < 2; ks++) {
            const int kk = ks * 16;
            uint32_t ah[4][4], al[4][4];
#pragma unroll
            for (int mt = 0; mt < 4; mt++) {
                const int r0 = warp_m + mt * 16 + qr;
                ah[mt][0] = *(const uint32_t*)&sAh[r0 * SSTR + kk + qc];
                ah[mt][1] = *(const uint32_t*)&sAh[(r0 + 8) * SSTR + kk + qc];
                ah[mt][2] = *(const uint32_t*)&sAh[r0 * SSTR + kk + 8 + qc];
                ah[mt][3] = *(const uint32_t*)&sAh[(r0 + 8) * SSTR + kk + 8 + qc];
                al[mt][0] = *(const uint32_t*)&sAl[r0 * SSTR + kk + qc];
                al[mt][1] = *(const uint32_t*)&sAl[(r0 + 8) * SSTR + kk + qc];
                al[mt][2] = *(const uint32_t*)&sAl[r0 * SSTR + kk + 8 + qc];
                al[mt][3] = *(const uint32_t*)&sAl[(r0 + 8) * SSTR + kk + 8 + qc];
            }
#pragma unroll
            for (int nt = 0; nt < 4; nt++) {
                const int nr = warp_n + nt * 8 + qr;
                const uint32_t bh0 = *(const uint32_t*)&sBh[nr * SSTR + kk + qc];
                const uint32_t bh1 = *(const uint32_t*)&sBh[nr * SSTR + kk + 8 + qc];
                const uint32_t bl0 = *(const uint32_t*)&sBl[nr * SSTR + kk + qc];
                const uint32_t bl1 = *(const uint32_t*)&sBl[nr * SSTR + kk + 8 + qc];
#pragma unroll
                for (int mt = 0; mt < 4; mt++) {
                    mma16816(d[mt][nt], ah[mt], bh0, bh1);
                    mma16816(d[mt][nt], ah[mt], bl0, bl1);
                    mma16816(d[mt][nt], al[mt], bh0, bh1);
                }
            }
        }
        __syncthreads();
    }

#pragma unroll
    for (int nt = 0; nt < 4; nt++) {
        const int gcol = n0 + warp_n + nt * 8 + qc;
        float* out;
        int col;
        float bv0 = 0.f, bv1 = 0.f;
        if (gcol < 256) {
            out = Ch;  col = gcol;
        } else {
            out = Cacc;  col = gcol - 256;
            bv0 = bias1[col] + bias2[col];
            bv1 = bias1[col + 1] + bias2[col + 1];
        }
#pragma unroll
        for (int mt = 0; mt < 4; mt++) {
            const int r0 = m0 + warp_m + mt * 16 + qr;
            if (r0 < M) {
                float2 v = make_float2(d[mt][nt][0] + bv0, d[mt][nt][1] + bv1);
                *(float2*)&out[(size_t)r0 * HC + col] = v;
            }
            if (r0 + 8 < M) {
                float2 v = make_float2(d[mt][nt][2] + bv0, d[mt][nt][3] + bv1);
                *(float2*)&out[(size_t)(r0 + 8) * HC + col] = v;
            }
        }
    }
}

// ------------------------- CSR build ---------------------------------------
__global__ void hist_kernel(const int* __restrict__ ei, int* __restrict__ deg,
                            int nE, int nTot) {
    const int e = blockIdx.x * blockDim.x + threadIdx.x;
    if (e >= nTot) return;
    const int d = (e < nE) ? ei[nE + e] : (e - nE);
    atomicAdd(&deg[d], 1);
}

__global__ __launch_bounds__(1024)
void scan_kernel(const int* __restrict__ deg, int* __restrict__ rp,
                 int* __restrict__ cur, int n) {
    __shared__ int part[1024];
    const int t = threadIdx.x;
    const int CH = (n + 1023) / 1024;
    const int start = t * CH;
    int s = 0;
    for (int i = 0; i < CH; i++) {
        const int idx = start + i;
        if (idx < n) s += deg[idx];
    }
    part[t] = s;
    __syncthreads();
    for (int off = 1; off < 1024; off <<= 1) {
        int v = (t >= off) ? part[t - off] : 0;
        __syncthreads();
        part[t] += v;
        __syncthreads();
    }
    int base = (t == 0) ? 0 : part[t - 1];
    for (int i = 0; i < CH; i++) {
        const int idx = start + i;
        if (idx < n) {
            rp[idx] = base;
            cur[idx] = base;
            base += deg[idx];
        }
    }
    if (t == 1023) rp[n] = part[1023];
}

__global__ void scatter_kernel(const int* __restrict__ ei, int* __restrict__ cur,
                               int* __restrict__ csr, int nE, int nTot) {
    const int e = blockIdx.x * blockDim.x + threadIdx.x;
    if (e >= nTot) return;
    int s, d;
    if (e < nE) { s = ei[e]; d = ei[nE + e]; }
    else        { s = d = e - nE; }
    const int pos = atomicAdd(&cur[d], 1);
    csr[pos] = s;
}

// ------------------------- s/d per node ------------------------------------
__global__ void compute_sd_kernel(const float* __restrict__ gh,
                                  const float* __restrict__ a_src,
                                  const float* __restrict__ a_dst,
                                  float* __restrict__ gs, float* __restrict__ gd,
                                  int n_nodes) {
    const int warp = (blockIdx.x * blockDim.x + threadIdx.x) >> 5;
    const int lane = threadIdx.x & 31;
    if (warp >= n_nodes) return;
    const float* hr = gh + (size_t)warp * HC;
#pragma unroll
    for (int h = 0; h < 4; h++) {
        const float h1 = hr[h * 64 + lane];
        const float h2 = hr[h * 64 + 32 + lane];
        float s = h1 * a_src[h * 64 + lane] + h2 * a_src[h * 64 + 32 + lane];
        float d = h1 * a_dst[h * 64 + lane] + h2 * a_dst[h * 64 + 32 + lane];
#pragma unroll
        for (int off = 16; off > 0; off >>= 1) {
            s += __shfl_down_sync(0xFFFFFFFFu, s, off);
            d += __shfl_down_sync(0xFFFFFFFFu, d, off);
        }
        if (lane == 0) {
            gs[warp * 4 + h] = s;
            gd[warp * 4 + h] = d;
        }
    }
}

// ------------------------- fused softmax + aggregate + skip + ELU ----------
__global__ __launch_bounds__(256)
void node_agg_kernel(const int* __restrict__ rp, const int* __restrict__ csr,
                     const float* __restrict__ gs, const float* __restrict__ gd,
                     const float* __restrict__ gh, const float* __restrict__ gskip,
                     float* __restrict__ xout,
                     __nv_bfloat16* __restrict__ xh,
                     __nv_bfloat16* __restrict__ xl,
                     int nN) {
    const int v = (blockIdx.x * blockDim.x + threadIdx.x) >> 5;
    const int lane = threadIdx.x & 31;
    if (v >= nN) return;

    const int b = rp[v];
    const int e = rp[v + 1];
    const float4 dv = ((const float4*)gd)[v];

    // pass 1: per-head max
    float m0 = -1e30f, m1 = -1e30f, m2 = -1e30f, m3 = -1e30f;
    for (int i = b + lane; i < e; i += 32) {
        const float4 sv = ((const float4*)gs)[csr[i]];
        m0 = fmaxf(m0, lrelu(sv.x + dv.x));
        m1 = fmaxf(m1, lrelu(sv.y + dv.y));
        m2 = fmaxf(m2, lrelu(sv.z + dv.z));
        m3 = fmaxf(m3, lrelu(sv.w + dv.w));
    }
#pragma unroll
    for (int off = 16; off > 0; off >>= 1) {
        m0 = fmaxf(m0, __shfl_xor_sync(0xFFFFFFFFu, m0, off));
        m1 = fmaxf(m1, __shfl_xor_sync(0xFFFFFFFFu, m1, off));
        m2 = fmaxf(m2, __shfl_xor_sync(0xFFFFFFFFu, m2, off));
        m3 = fmaxf(m3, __shfl_xor_sync(0xFFFFFFFFu, m3, off));
    }

    // pass 2: denominators
    float n0 = 0.f, n1 = 0.f, n2 = 0.f, n3 = 0.f;
    for (int i = b + lane; i < e; i += 32) {
        const float4 sv = ((const float4*)gs)[csr[i]];
        n0 += expf(lrelu(sv.x + dv.x) - m0);
        n1 += expf(lrelu(sv.y + dv.y) - m1);
        n2 += expf(lrelu(sv.z + dv.z) - m2);
        n3 += expf(lrelu(sv.w + dv.w) - m3);
    }
#pragma unroll
    for (int off = 16; off > 0; off >>= 1) {
        n0 += __shfl_xor_sync(0xFFFFFFFFu, n0, off);
        n1 += __shfl_xor_sync(0xFFFFFFFFu, n1, off);
        n2 += __shfl_xor_sync(0xFFFFFFFFu, n2, off);
        n3 += __shfl_xor_sync(0xFFFFFFFFu, n3, off);
    }

    const int h = lane >> 3;
    const float dvh  = (h < 2) ? (h == 0 ? dv.x : dv.y) : (h == 2 ? dv.z : dv.w);
    const float mh   = (h < 2) ? (h == 0 ? m0 : m1) : (h == 2 ? m2 : m3);
    const float dnh  = (h < 2) ? (h == 0 ? n0 : n1) : (h == 2 ? n2 : n3);
    const float invh = 1.f / (dnh + 1e-16f);

    // pass 3: gather h[src] * alpha; lane owns channels [lane*8, lane*8+8)
    float4 a0 = make_float4(0.f, 0.f, 0.f, 0.f);
    float4 a1 = make_float4(0.f, 0.f, 0.f, 0.f);
#pragma unroll 2
    for (int i = b; i < e; i++) {
        const int s = csr[i];
        const float sval = gs[s * 4 + h];
        const float al = expf(lrelu(sval + dvh) - mh) * invh;
        const float4* hp = (const float4*)(gh + (size_t)s * HC) + lane * 2;
        const float4 v0 = hp[0];
        const float4 v1 = hp[1];
        a0.x = fmaf(v0.x, al, a0.x);  a0.y = fmaf(v0.y, al, a0.y);
        a0.z = fmaf(v0.z, al, a0.z);  a0.w = fmaf(v0.w, al, a0.w);
        a1.x = fmaf(v1.x, al, a1.x);  a1.y = fmaf(v1.y, al, a1.y);
        a1.z = fmaf(v1.z, al, a1.z);  a1.w = fmaf(v1.w, al, a1.w);
    }

    // skip + ELU
    const float4* sp = (const float4*)(gskip + (size_t)v * HC) + lane * 2;
    const float4 s0 = sp[0];
    const float4 s1 = sp[1];
    float4 o0, o1;
    o0.x = a0.x + s0.x;  o0.y = a0.y + s0.y;  o0.z = a0.z + s0.z;  o0.w = a0.w + s0.w;
    o1.x = a1.x + s1.x;  o1.y = a1.y + s1.y;  o1.z = a1.z + s1.z;  o1.w = a1.w + s1.w;
    o0.x = o0.x > 0.f ? o0.x : expm1f(o0.x);
    o0.y = o0.y > 0.f ? o0.y : expm1f(o0.y);
    o0.z = o0.z > 0.f ? o0.z : expm1f(o0.z);
    o0.w = o0.w > 0.f ? o0.w : expm1f(o0.w);
    o1.x = o1.x > 0.f ? o1.x : expm1f(o1.x);
    o1.y = o1.y > 0.f ? o1.y : expm1f(o1.y);
    o1.z = o1.z > 0.f ? o1.z : expm1f(o1.z);
    o1.w = o1.w > 0.f ? o1.w : expm1f(o1.w);
    float4* op = (float4*)(xout + (size_t)v * HC) + lane * 2;
    op[0] = o0;
    op[1] = o1;

    // bf16 hi/lo split for next layer's GEMM input
    if (xh) {
        __nv_bfloat162 h0 = __floats2bfloat162_rn(o0.x, o0.y);
        __nv_bfloat162 h1 = __floats2bfloat162_rn(o0.z, o0.w);
        __nv_bfloat162 h2 = __floats2bfloat162_rn(o1.x, o1.y);
        __nv_bfloat162 h3 = __floats2bfloat162_rn(o1.z, o1.w);
        __nv_bfloat162 l0 = __floats2bfloat162_rn(o0.x - __low2float(h0), o0.y - __high2float(h0));
        __nv_bfloat162 l1 = __floats2bfloat162_rn(o0.z - __low2float(h1), o0.w - __high2float(h1));
        __nv_bfloat162 l2 = __floats2bfloat162_rn(o1.x - __low2float(h2), o1.y - __high2float(h2));
        __nv_bfloat162 l3 = __floats2bfloat162_rn(o1.z - __low2float(h3), o1.w - __high2float(h3));
        uint4 uh = make_uint4(*(uint32_t*)&h0, *(uint32_t*)&h1, *(uint32_t*)&h2, *(uint32_t*)&h3);
        uint4 ul = make_uint4(*(uint32_t*)&l0, *(uint32_t*)&l1, *(uint32_t*)&l2, *(uint32_t*)&l3);
        *(uint4*)(xh + (size_t)v * HC + lane * 8) = uh;
        *(uint4*)(xl + (size_t)v * HC + lane * 8) = ul;
    }
}

// ---------------------------------------------------------------------------
extern "C" void kernel_launch(void* const* d_in, const int* in_sizes, int n_in,
                              void* d_out, int out_size) {
    const float* x0 = (const float*)d_in[0];
    const int* ei = (const int*)d_in[1];
    const int nE = in_sizes[1] / 2;
    const int nN = NNODES;
    const int nTot = nE + nN;

    const float* W[3]    = {(const float*)d_in[2],  (const float*)d_in[8],  (const float*)d_in[14]};
    const float* ASRC[3] = {(const float*)d_in[3],  (const float*)d_in[9],  (const float*)d_in[15]};
    const float* ADST[3] = {(const float*)d_in[4],  (const float*)d_in[10], (const float*)d_in[16]};
    const float* BB[3]   = {(const float*)d_in[5],  (const float*)d_in[11], (const float*)d_in[17]};
    const float* SW[3]   = {(const float*)d_in[6],  (const float*)d_in[12], (const float*)d_in[18]};
    const float* SB[3]   = {(const float*)d_in[7],  (const float*)d_in[13], (const float*)d_in[19]};
    const int FIN[3] = {128, HC, HC};

    float *ph, *pacc, *px, *ps, *pd;
    int *pdeg, *pcur, *prp, *pcsr;
    __nv_bfloat16 *pbh, *pbl, *pah, *pal;
    cudaGetSymbolAddress((void**)&ph,   g_h);
    cudaGetSymbolAddress((void**)&pacc, g_acc);
    cudaGetSymbolAddress((void**)&px,   g_x);
    cudaGetSymbolAddress((void**)&ps,   g_s);
    cudaGetSymbolAddress((void**)&pd,   g_d);
    cudaGetSymbolAddress((void**)&pdeg, g_deg);
    cudaGetSymbolAddress((void**)&pcur, g_cur);
    cudaGetSymbolAddress((void**)&prp,  g_rp);
    cudaGetSymbolAddress((void**)&pcsr, g_csr);
    cudaGetSymbolAddress((void**)&pbh,  g_bh);
    cudaGetSymbolAddress((void**)&pbl,  g_bl);
    cudaGetSymbolAddress((void**)&pah,  g_ah);
    cudaGetSymbolAddress((void**)&pal,  g_al);

    // launch 0: all weight splits + deg zeroing
    prep_kernel<<<1280, 256>>>(W[0], SW[0], W[1], SW[1], W[2], SW[2],
                               pbh, pbl, pdeg);
    // launch 1: layer-1 input split (K=128)
    conv_a_kernel<<<(nN * 128 + 255) / 256, 256>>>(x0, pah, pal, nN * 128);
    // launches 2-4: CSR build
    const int eBlocks = (nTot + 255) / 256;
    hist_kernel<<<eBlocks, 256>>>(ei, pdeg, nE, nTot);
    scan_kernel<<<1, 1024>>>(pdeg, prp, pcur, nN);
    scatter_kernel<<<eBlocks, 256>>>(ei, pcur, pcsr, nE, nTot);

    const dim3 gemmGrid(4, (nN + 127) / 128);
    const int sdBlocks  = (nN * 32 + 255) / 256;
    const int aggBlocks = (nN * 32 + 255) / 256;

    for (int l = 0; l < 3; l++) {
        const int K = FIN[l];
        __nv_bfloat16* bh = pbh + (size_t)l * 131072;
        __nv_bfloat16* bl = pbl + (size_t)l * 131072;
        // launch 5 (first gemm) — profiled by ncu -s 5 -c 1
        gemm_mma_kernel<<<gemmGrid, 256>>>(pah, pal, bh, bl, ph, pacc,
                                           BB[l], SB[l], nN, K);
        compute_sd_kernel<<<sdBlocks, 256>>>(ph, ASRC[l], ADST[l], ps, pd, nN);
        float* xout = (l == 2) ? (float*)d_out : px;
        __nv_bfloat16* xh = (l == 2) ? nullptr : pah;
        __nv_bfloat16* xl = (l == 2) ? nullptr : pal;
        node_agg_kernel<<<aggBlocks, 256>>>(prp, pcsr, ps, pd, ph, pacc,
                                            xout, xh, xl, nN);
    }
}

// round 9
// speedup vs baseline: 1.1374x; 1.0922x over previous
#include <cuda_runtime.h>
#include <cuda_bf16.h>
#include <cstdint>

// ---------------------------------------------------------------------------
// GATEncoder: 3 layers of (GATConv + linear skip + ELU)
// N=50000, E=800000 (+N self loops), IN=128, H=4, C=64, HC=256
// Round 9: parallel 3-phase CSR scan (was 75us single-block);
//          layer-1 GEMM hoisted to my-launch #3 so ncu -s 5 profiles it.
// ---------------------------------------------------------------------------

#define NNODES 50000
#define NEDGES 800000
#define ETOT   (NEDGES + NNODES)
#define HC     256
#define SCAN_BLK 512

// ------------------------- static device scratch ---------------------------
__device__ float g_h   [(size_t)NNODES * HC];
__device__ float g_acc [(size_t)NNODES * HC];
__device__ float g_x   [(size_t)NNODES * HC];
__device__ float g_s   [(size_t)NNODES * 4];
__device__ float g_d   [(size_t)NNODES * 4];
__device__ int   g_deg [NNODES];
__device__ int   g_cur [NNODES];
__device__ int   g_rp  [NNODES + 1];
__device__ int   g_csr [ETOT];
__device__ int   g_bsum[256];
__device__ __nv_bfloat16 g_ah[(size_t)NNODES * HC];
__device__ __nv_bfloat16 g_al[(size_t)NNODES * HC];
__device__ __nv_bfloat16 g_bh[3][131072];
__device__ __nv_bfloat16 g_bl[3][131072];

// ------------------------- helpers ----------------------------------------
__device__ __forceinline__ float lrelu(float v) { return v > 0.f ? v : 0.2f * v; }

__device__ __forceinline__ void mma16816(float* d, const uint32_t* a,
                                         uint32_t b0, uint32_t b1) {
    asm volatile(
        "mma.sync.aligned.m16n8k16.row.col.f32.bf16.bf16.f32 "
        "{%0,%1,%2,%3}, {%4,%5,%6,%7}, {%8,%9}, {%0,%1,%2,%3};"
        : "+f"(d[0]), "+f"(d[1]), "+f"(d[2]), "+f"(d[3])
        : "r"(a[0]), "r"(a[1]), "r"(a[2]), "r"(a[3]), "r"(b0), "r"(b1));
}

// ------------------------- prep: all weight splits + deg zero --------------
__global__ void prep_kernel(const float* __restrict__ W1, const float* __restrict__ SW1,
                            const float* __restrict__ W2, const float* __restrict__ SW2,
                            const float* __restrict__ W3, const float* __restrict__ SW3,
                            __nv_bfloat16* __restrict__ bh,
                            __nv_bfloat16* __restrict__ bl,
                            int* __restrict__ deg) {
    const int idx = blockIdx.x * blockDim.x + threadIdx.x;
    if (idx < NNODES) deg[idx] = 0;
    if (idx >= 327680) return;
    int l, which, mi, K;
    const float* src;
    if (idx < 65536)       { l = 0; K = 128; const int r = idx;          which = r >> 15; mi = r & 32767; src = which ? SW1 : W1; }
    else if (idx < 196608) { l = 1; K = 256; const int r = idx - 65536;  which = r >> 16; mi = r & 65535; src = which ? SW2 : W2; }
    else                   { l = 2; K = 256; const int r = idx - 196608; which = r >> 16; mi = r & 65535; src = which ? SW3 : W3; }
    const int k = mi >> 8;
    const int n = mi & 255;
    const float v = src[mi];
    const __nv_bfloat16 h = __float2bfloat16(v);
    const size_t off = (size_t)l * 131072 + (size_t)(which * 256 + n) * K + k;
    bh[off] = h;
    bl[off] = __float2bfloat16(v - __bfloat162float(h));
}

// ------------------------- conv_a: fp32 -> bf16 hi/lo (layer-1 input) ------
__global__ void conv_a_kernel(const float* __restrict__ X,
                              __nv_bfloat16* __restrict__ ah,
                              __nv_bfloat16* __restrict__ al, int total) {
    const int idx = blockIdx.x * blockDim.x + threadIdx.x;
    if (idx >= total) return;
    const float v = X[idx];
    const __nv_bfloat16 h = __float2bfloat16(v);
    ah[idx] = h;
    al[idx] = __float2bfloat16(v - __bfloat162float(h));
}

// ------------------------- fused dual GEMM (mma.sync bf16 split) -----------
#define SSTR 40

__global__ __launch_bounds__(256, 2)
void gemm_mma_kernel(const __nv_bfloat16* __restrict__ Ah,
                     const __nv_bfloat16* __restrict__ Al,
                     const __nv_bfloat16* __restrict__ Bh,
                     const __nv_bfloat16* __restrict__ Bl,
                     float* __restrict__ Ch,
                     float* __restrict__ Cacc,
                     const float* __restrict__ bias1,
                     const float* __restrict__ bias2,
                     int M, int K) {
    __shared__ __nv_bfloat16 sAh[128 * SSTR];
    __shared__ __nv_bfloat16 sAl[128 * SSTR];
    __shared__ __nv_bfloat16 sBh[128 * SSTR];
    __shared__ __nv_bfloat16 sBl[128 * SSTR];

    const int tid = threadIdx.x;
    const int wid = tid >> 5;
    const int lane = tid & 31;
    const int qr = lane >> 2;
    const int qc = (lane & 3) * 2;
    const int warp_m = (wid >> 2) * 64;
    const int warp_n = (wid & 3) * 32;
    const int m0 = blockIdx.y * 128;
    const int n0 = blockIdx.x * 128;

    float d[4][4][4];
#pragma unroll
    for (int mt = 0; mt < 4; mt++)
#pragma unroll
        for (int nt = 0; nt < 4; nt++)
#pragma unroll
            for (int r = 0; r < 4; r++) d[mt][nt][r] = 0.f;

    const int ar = tid >> 1;
    const int akh = (tid & 1) * 16;
    const int bn = tid >> 1;
    const int bkh = (tid & 1) * 16;

    const int nch = K >> 5;
    for (int ch = 0; ch < nch; ch++) {
        const int k0 = ch << 5;
        {
            uint4 vh0 = make_uint4(0u, 0u, 0u, 0u), vh1 = vh0;
            uint4 vl0 = vh0, vl1 = vh0;
            if (m0 + ar < M) {
                const size_t off = (size_t)(m0 + ar) * K + k0 + akh;
                vh0 = *(const uint4*)&Ah[off];
                vh1 = *(const uint4*)&Ah[off + 8];
                vl0 = *(const uint4*)&Al[off];
                vl1 = *(const uint4*)&Al[off + 8];
            }
            *(uint4*)&sAh[ar * SSTR + akh]     = vh0;
            *(uint4*)&sAh[ar * SSTR + akh + 8] = vh1;
            *(uint4*)&sAl[ar * SSTR + akh]     = vl0;
            *(uint4*)&sAl[ar * SSTR + akh + 8] = vl1;
        }
        {
            const size_t goff = (size_t)(n0 + bn) * K + k0 + bkh;
            const uint4 wh0 = *(const uint4*)&Bh[goff];
            const uint4 wh1 = *(const uint4*)&Bh[goff + 8];
            const uint4 wl0 = *(const uint4*)&Bl[goff];
            const uint4 wl1 = *(const uint4*)&Bl[goff + 8];
            *(uint4*)&sBh[bn * SSTR + bkh]     = wh0;
            *(uint4*)&sBh[bn * SSTR + bkh + 8] = wh1;
            *(uint4*)&sBl[bn * SSTR + bkh]     = wl0;
            *(uint4*)&sBl[bn * SSTR + bkh + 8] = wl1;
        }
        __syncthreads();

#pragma unroll
        for (int ks = 0; ks < 2; ks++) {
            const int kk = ks * 16;
            uint32_t ah[4][4], al[4][4];
#pragma unroll
            for (int mt = 0; mt < 4; mt++) {
                const int r0 = warp_m + mt * 16 + qr;
                ah[mt][0] = *(const uint32_t*)&sAh[r0 * SSTR + kk + qc];
                ah[mt][1] = *(const uint32_t*)&sAh[(r0 + 8) * SSTR + kk + qc];
                ah[mt][2] = *(const uint32_t*)&sAh[r0 * SSTR + kk + 8 + qc];
                ah[mt][3] = *(const uint32_t*)&sAh[(r0 + 8) * SSTR + kk + 8 + qc];
                al[mt][0] = *(const uint32_t*)&sAl[r0 * SSTR + kk + qc];
                al[mt][1] = *(const uint32_t*)&sAl[(r0 + 8) * SSTR + kk + qc];
                al[mt][2] = *(const uint32_t*)&sAl[r0 * SSTR + kk + 8 + qc];
                al[mt][3] = *(const uint32_t*)&sAl[(r0 + 8) * SSTR + kk + 8 + qc];
            }
#pragma unroll
            for (int nt = 0; nt < 4; nt++) {
                const int nr = warp_n + nt * 8 + qr;
                const uint32_t bh0 = *(const uint32_t*)&sBh[nr * SSTR + kk + qc];
                const uint32_t bh1 = *(const uint32_t*)&sBh[nr * SSTR + kk + 8 + qc];
                const uint32_t bl0 = *(const uint32_t*)&sBl[nr * SSTR + kk + qc];
                const uint32_t bl1 = *(const uint32_t*)&sBl[nr * SSTR + kk + 8 + qc];
#pragma unroll
                for (int mt = 0; mt < 4; mt++) {
                    mma16816(d[mt][nt], ah[mt], bh0, bh1);
                    mma16816(d[mt][nt], ah[mt], bl0, bl1);
                    mma16816(d[mt][nt], al[mt], bh0, bh1);
                }
            }
        }
        __syncthreads();
    }

#pragma unroll
    for (int nt = 0; nt < 4; nt++) {
        const int gcol = n0 + warp_n + nt * 8 + qc;
        float* out;
        int col;
        float bv0 = 0.f, bv1 = 0.f;
        if (gcol < 256) {
            out = Ch;  col = gcol;
        } else {
            out = Cacc;  col = gcol - 256;
            bv0 = bias1[col] + bias2[col];
            bv1 = bias1[col + 1] + bias2[col + 1];
        }
#pragma unroll
        for (int mt = 0; mt < 4; mt++) {
            const int r0 = m0 + warp_m + mt * 16 + qr;
            if (r0 < M) {
                float2 v = make_float2(d[mt][nt][0] + bv0, d[mt][nt][1] + bv1);
                *(float2*)&out[(size_t)r0 * HC + col] = v;
            }
            if (r0 + 8 < M) {
                float2 v = make_float2(d[mt][nt][2] + bv0, d[mt][nt][3] + bv1);
                *(float2*)&out[(size_t)(r0 + 8) * HC + col] = v;
            }
        }
    }
}

// ------------------------- CSR build ---------------------------------------
__global__ void hist_kernel(const int* __restrict__ ei, int* __restrict__ deg,
                            int nE, int nTot) {
    const int e = blockIdx.x * blockDim.x + threadIdx.x;
    if (e >= nTot) return;
    const int d = (e < nE) ? ei[nE + e] : (e - nE);
    atomicAdd(&deg[d], 1);
}

// phase 1: per-block (512 elems) reduction
__global__ void scan1_kernel(const int* __restrict__ deg, int* __restrict__ bsum,
                             int n) {
    __shared__ int sh[256];
    const int b0 = blockIdx.x * SCAN_BLK;
    const int t = threadIdx.x;
    int s = 0;
    if (b0 + t < n)       s += deg[b0 + t];
    if (b0 + 256 + t < n) s += deg[b0 + 256 + t];
    sh[t] = s;
    __syncthreads();
    for (int off = 128; off > 0; off >>= 1) {
        if (t < off) sh[t] += sh[t + off];
        __syncthreads();
    }
    if (t == 0) bsum[blockIdx.x] = sh[0];
}

// phase 2: exclusive scan of <=256 block sums (in place)
__global__ void scan2_kernel(int* __restrict__ bsum, int nb) {
    __shared__ int sh[256];
    const int t = threadIdx.x;
    sh[t] = (t < nb) ? bsum[t] : 0;
    __syncthreads();
    for (int off = 1; off < 256; off <<= 1) {
        const int v = (t >= off) ? sh[t - off] : 0;
        __syncthreads();
        sh[t] += v;
        __syncthreads();
    }
    if (t < nb) bsum[t] = (t == 0) ? 0 : sh[t - 1];
}

// phase 3: per-block inclusive scan + base -> exclusive rp/cur
__global__ void scan3_kernel(const int* __restrict__ deg,
                             const int* __restrict__ bsum,
                             int* __restrict__ rp, int* __restrict__ cur,
                             int n) {
    __shared__ int sh[SCAN_BLK];
    const int b0 = blockIdx.x * SCAN_BLK;
    const int t = threadIdx.x;
    const int v0 = (b0 + t < n) ? deg[b0 + t] : 0;
    const int v1 = (b0 + 256 + t < n) ? deg[b0 + 256 + t] : 0;
    sh[t] = v0;
    sh[256 + t] = v1;
    __syncthreads();
    for (int off = 1; off < SCAN_BLK; off <<= 1) {
        const int a0 = (t >= off) ? sh[t - off] : 0;
        const int a1 = (t + 256 >= off) ? sh[t + 256 - off] : 0;
        __syncthreads();
        sh[t] += a0;
        sh[256 + t] += a1;
        __syncthreads();
    }
    const int base = bsum[blockIdx.x];
    if (b0 + t < n) {
        const int ex = base + sh[t] - v0;
        rp[b0 + t] = ex;
        cur[b0 + t] = ex;
    }
    if (b0 + 256 + t < n) {
        const int ex = base + sh[256 + t] - v1;
        rp[b0 + 256 + t] = ex;
        cur[b0 + 256 + t] = ex;
    }
    if (blockIdx.x == gridDim.x - 1 && t == 0) rp[n] = base + sh[SCAN_BLK - 1];
}

__global__ void scatter_kernel(const int* __restrict__ ei, int* __restrict__ cur,
                               int* __restrict__ csr, int nE, int nTot) {
    const int e = blockIdx.x * blockDim.x + threadIdx.x;
    if (e >= nTot) return;
    int s, d;
    if (e < nE) { s = ei[e]; d = ei[nE + e]; }
    else        { s = d = e - nE; }
    const int pos = atomicAdd(&cur[d], 1);
    csr[pos] = s;
}

// ------------------------- s/d per node ------------------------------------
__global__ void compute_sd_kernel(const float* __restrict__ gh,
                                  const float* __restrict__ a_src,
                                  const float* __restrict__ a_dst,
                                  float* __restrict__ gs, float* __restrict__ gd,
                                  int n_nodes) {
    const int warp = (blockIdx.x * blockDim.x + threadIdx.x) >> 5;
    const int lane = threadIdx.x & 31;
    if (warp >= n_nodes) return;
    const float* hr = gh + (size_t)warp * HC;
#pragma unroll
    for (int h = 0; h < 4; h++) {
        const float h1 = hr[h * 64 + lane];
        const float h2 = hr[h * 64 + 32 + lane];
        float s = h1 * a_src[h * 64 + lane] + h2 * a_src[h * 64 + 32 + lane];
        float d = h1 * a_dst[h * 64 + lane] + h2 * a_dst[h * 64 + 32 + lane];
#pragma unroll
        for (int off = 16; off > 0; off >>= 1) {
            s += __shfl_down_sync(0xFFFFFFFFu, s, off);
            d += __shfl_down_sync(0xFFFFFFFFu, d, off);
        }
        if (lane == 0) {
            gs[warp * 4 + h] = s;
            gd[warp * 4 + h] = d;
        }
    }
}

// ------------------------- fused softmax + aggregate + skip + ELU ----------
__global__ __launch_bounds__(256)
void node_agg_kernel(const int* __restrict__ rp, const int* __restrict__ csr,
                     const float* __restrict__ gs, const float* __restrict__ gd,
                     const float* __restrict__ gh, const float* __restrict__ gskip,
                     float* __restrict__ xout,
                     __nv_bfloat16* __restrict__ xh,
                     __nv_bfloat16* __restrict__ xl,
                     int nN) {
    const int v = (blockIdx.x * blockDim.x + threadIdx.x) >> 5;
    const int lane = threadIdx.x & 31;
    if (v >= nN) return;

    const int b = rp[v];
    const int e = rp[v + 1];
    const float4 dv = ((const float4*)gd)[v];

    float m0 = -1e30f, m1 = -1e30f, m2 = -1e30f, m3 = -1e30f;
    for (int i = b + lane; i < e; i += 32) {
        const float4 sv = ((const float4*)gs)[csr[i]];
        m0 = fmaxf(m0, lrelu(sv.x + dv.x));
        m1 = fmaxf(m1, lrelu(sv.y + dv.y));
        m2 = fmaxf(m2, lrelu(sv.z + dv.z));
        m3 = fmaxf(m3, lrelu(sv.w + dv.w));
    }
#pragma unroll
    for (int off = 16; off > 0; off >>= 1) {
        m0 = fmaxf(m0, __shfl_xor_sync(0xFFFFFFFFu, m0, off));
        m1 = fmaxf(m1, __shfl_xor_sync(0xFFFFFFFFu, m1, off));
        m2 = fmaxf(m2, __shfl_xor_sync(0xFFFFFFFFu, m2, off));
        m3 = fmaxf(m3, __shfl_xor_sync(0xFFFFFFFFu, m3, off));
    }

    float n0 = 0.f, n1 = 0.f, n2 = 0.f, n3 = 0.f;
    for (int i = b + lane; i < e; i += 32) {
        const float4 sv = ((const float4*)gs)[csr[i]];
        n0 += expf(lrelu(sv.x + dv.x) - m0);
        n1 += expf(lrelu(sv.y + dv.y) - m1);
        n2 += expf(lrelu(sv.z + dv.z) - m2);
        n3 += expf(lrelu(sv.w + dv.w) - m3);
    }
#pragma unroll
    for (int off = 16; off > 0; off >>= 1) {
        n0 += __shfl_xor_sync(0xFFFFFFFFu, n0, off);
        n1 += __shfl_xor_sync(0xFFFFFFFFu, n1, off);
        n2 += __shfl_xor_sync(0xFFFFFFFFu, n2, off);
        n3 += __shfl_xor_sync(0xFFFFFFFFu, n3, off);
    }

    const int h = lane >> 3;
    const float dvh  = (h < 2) ? (h == 0 ? dv.x : dv.y) : (h == 2 ? dv.z : dv.w);
    const float mh   = (h < 2) ? (h == 0 ? m0 : m1) : (h == 2 ? m2 : m3);
    const float dnh  = (h < 2) ? (h == 0 ? n0 : n1) : (h == 2 ? n2 : n3);
    const float invh = 1.f / (dnh + 1e-16f);

    float4 a0 = make_float4(0.f, 0.f, 0.f, 0.f);
    float4 a1 = make_float4(0.f, 0.f, 0.f, 0.f);
#pragma unroll 2
    for (int i = b; i < e; i++) {
        const int s = csr[i];
        const float sval = gs[s * 4 + h];
        const float al = expf(lrelu(sval + dvh) - mh) * invh;
        const float4* hp = (const float4*)(gh + (size_t)s * HC) + lane * 2;
        const float4 v0 = hp[0];
        const float4 v1 = hp[1];
        a0.x = fmaf(v0.x, al, a0.x);  a0.y = fmaf(v0.y, al, a0.y);
        a0.z = fmaf(v0.z, al, a0.z);  a0.w = fmaf(v0.w, al, a0.w);
        a1.x = fmaf(v1.x, al, a1.x);  a1.y = fmaf(v1.y, al, a1.y);
        a1.z = fmaf(v1.z, al, a1.z);  a1.w = fmaf(v1.w, al, a1.w);
    }

    const float4* sp = (const float4*)(gskip + (size_t)v * HC) + lane * 2;
    const float4 s0 = sp[0];
    const float4 s1 = sp[1];
    float4 o0, o1;
    o0.x = a0.x + s0.x;  o0.y = a0.y + s0.y;  o0.z = a0.z + s0.z;  o0.w = a0.w + s0.w;
    o1.x = a1.x + s1.x;  o1.y = a1.y + s1.y;  o1.z = a1.z + s1.z;  o1.w = a1.w + s1.w;
    o0.x = o0.x > 0.f ? o0.x : expm1f(o0.x);
    o0.y = o0.y > 0.f ? o0.y : expm1f(o0.y);
    o0.z = o0.z > 0.f ? o0.z : expm1f(o0.z);
    o0.w = o0.w > 0.f ? o0.w : expm1f(o0.w);
    o1.x = o1.x > 0.f ? o1.x : expm1f(o1.x);
    o1.y = o1.y > 0.f ? o1.y : expm1f(o1.y);
    o1.z = o1.z > 0.f ? o1.z : expm1f(o1.z);
    o1.w = o1.w > 0.f ? o1.w : expm1f(o1.w);
    float4* op = (float4*)(xout + (size_t)v * HC) + lane * 2;
    op[0] = o0;
    op[1] = o1;

    if (xh) {
        __nv_bfloat162 h0 = __floats2bfloat162_rn(o0.x, o0.y);
        __nv_bfloat162 h1 = __floats2bfloat162_rn(o0.z, o0.w);
        __nv_bfloat162 h2 = __floats2bfloat162_rn(o1.x, o1.y);
        __nv_bfloat162 h3 = __floats2bfloat162_rn(o1.z, o1.w);
        __nv_bfloat162 l0 = __floats2bfloat162_rn(o0.x - __low2float(h0), o0.y - __high2float(h0));
        __nv_bfloat162 l1 = __floats2bfloat162_rn(o0.z - __low2float(h1), o0.w - __high2float(h1));
        __nv_bfloat162 l2 = __floats2bfloat162_rn(o1.x - __low2float(h2), o1.y - __high2float(h2));
        __nv_bfloat162 l3 = __floats2bfloat162_rn(o1.z - __low2float(h3), o1.w - __high2float(h3));
        uint4 uh = make_uint4(*(uint32_t*)&h0, *(uint32_t*)&h1, *(uint32_t*)&h2, *(uint32_t*)&h3);
        uint4 ul = make_uint4(*(uint32_t*)&l0, *(uint32_t*)&l1, *(uint32_t*)&l2, *(uint32_t*)&l3);
        *(uint4*)(xh + (size_t)v * HC + lane * 8) = uh;
        *(uint4*)(xl + (size_t)v * HC + lane * 8) = ul;
    }
}

// ---------------------------------------------------------------------------
extern "C" void kernel_launch(void* const* d_in, const int* in_sizes, int n_in,
                              void* d_out, int out_size) {
    const float* x0 = (const float*)d_in[0];
    const int* ei = (const int*)d_in[1];
    const int nE = in_sizes[1] / 2;
    const int nN = NNODES;
    const int nTot = nE + nN;

    const float* W[3]    = {(const float*)d_in[2],  (const float*)d_in[8],  (const float*)d_in[14]};
    const float* ASRC[3] = {(const float*)d_in[3],  (const float*)d_in[9],  (const float*)d_in[15]};
    const float* ADST[3] = {(const float*)d_in[4],  (const float*)d_in[10], (const float*)d_in[16]};
    const float* BB[3]   = {(const float*)d_in[5],  (const float*)d_in[11], (const float*)d_in[17]};
    const float* SW[3]   = {(const float*)d_in[6],  (const float*)d_in[12], (const float*)d_in[18]};
    const float* SB[3]   = {(const float*)d_in[7],  (const float*)d_in[13], (const float*)d_in[19]};
    const int FIN[3] = {128, HC, HC};

    float *ph, *pacc, *px, *ps, *pd;
    int *pdeg, *pcur, *prp, *pcsr, *pbsum;
    __nv_bfloat16 *pbh, *pbl, *pah, *pal;
    cudaGetSymbolAddress((void**)&ph,   g_h);
    cudaGetSymbolAddress((void**)&pacc, g_acc);
    cudaGetSymbolAddress((void**)&px,   g_x);
    cudaGetSymbolAddress((void**)&ps,   g_s);
    cudaGetSymbolAddress((void**)&pd,   g_d);
    cudaGetSymbolAddress((void**)&pdeg, g_deg);
    cudaGetSymbolAddress((void**)&pcur, g_cur);
    cudaGetSymbolAddress((void**)&prp,  g_rp);
    cudaGetSymbolAddress((void**)&pcsr, g_csr);
    cudaGetSymbolAddress((void**)&pbsum,g_bsum);
    cudaGetSymbolAddress((void**)&pbh,  g_bh);
    cudaGetSymbolAddress((void**)&pbl,  g_bl);
    cudaGetSymbolAddress((void**)&pah,  g_ah);
    cudaGetSymbolAddress((void**)&pal,  g_al);

    const dim3 gemmGrid(4, (nN + 127) / 128);
    const int eBlocks   = (nTot + 255) / 256;
    const int sdBlocks  = (nN * 32 + 255) / 256;
    const int aggBlocks = (nN * 32 + 255) / 256;
    const int scanBlocks = (nN + SCAN_BLK - 1) / SCAN_BLK;

    // my-launch 0..2: prep, conv_a, hist
    prep_kernel<<<1280, 256>>>(W[0], SW[0], W[1], SW[1], W[2], SW[2],
                               pbh, pbl, pdeg);
    conv_a_kernel<<<(nN * 128 + 255) / 256, 256>>>(x0, pah, pal, nN * 128);
    hist_kernel<<<eBlocks, 256>>>(ei, pdeg, nE, nTot);

    // my-launch 3: layer-1 GEMM (profiled by ncu -s 5 -c 1)
    gemm_mma_kernel<<<gemmGrid, 256>>>(pah, pal, pbh, pbl, ph, pacc,
                                       BB[0], SB[0], nN, 128);

    // CSR build: parallel 3-phase scan + scatter
    scan1_kernel<<<scanBlocks, 256>>>(pdeg, pbsum, nN);
    scan2_kernel<<<1, 256>>>(pbsum, scanBlocks);
    scan3_kernel<<<scanBlocks, 256>>>(pdeg, pbsum, prp, pcur, nN);
    scatter_kernel<<<eBlocks, 256>>>(ei, pcur, pcsr, nE, nTot);

    for (int l = 0; l < 3; l++) {
        if (l > 0) {
            __nv_bfloat16* bh = pbh + (size_t)l * 131072;
            __nv_bfloat16* bl = pbl + (size_t)l * 131072;
            gemm_mma_kernel<<<gemmGrid, 256>>>(pah, pal, bh, bl, ph, pacc,
                                               BB[l], SB[l], nN, FIN[l]);
        }
        compute_sd_kernel<<<sdBlocks, 256>>>(ph, ASRC[l], ADST[l], ps, pd, nN);
        float* xout = (l == 2) ? (float*)d_out : px;
        __nv_bfloat16* xh = (l == 2) ? nullptr : pah;
        __nv_bfloat16* xl = (l == 2) ? nullptr : pal;
        node_agg_kernel<<<aggBlocks, 256>>>(prp, pcsr, ps, pd, ph, pacc,
                                            xout, xh, xl, nN);
    }
}

// round 10
// speedup vs baseline: 1.2183x; 1.0711x over previous
#include <cuda_runtime.h>
#include <cuda_bf16.h>
#include <cstdint>

// ---------------------------------------------------------------------------
// GATEncoder: 3 layers of (GATConv + linear skip + ELU)
// N=50000, E=800000 (+N self loops), IN=128, H=4, C=64, HC=256
// Round 10: cp.async double-buffered GEMM pipeline (2-stage dynamic smem).
//           Compute/fragment math identical to round 9 (verified).
// ---------------------------------------------------------------------------

#define NNODES 50000
#define NEDGES 800000
#define ETOT   (NEDGES + NNODES)
#define HC     256
#define SCAN_BLK 512
#define SSTR 40
#define STG  (128 * SSTR)                 // elems per matrix per stage
#define GEMM_SMEM (2 * 4 * STG * 2)       // bytes: 2 stages x 4 matrices x bf16

// ------------------------- static device scratch ---------------------------
__device__ float g_h   [(size_t)NNODES * HC];
__device__ float g_acc [(size_t)NNODES * HC];
__device__ float g_x   [(size_t)NNODES * HC];
__device__ float g_s   [(size_t)NNODES * 4];
__device__ float g_d   [(size_t)NNODES * 4];
__device__ int   g_deg [NNODES];
__device__ int   g_cur [NNODES];
__device__ int   g_rp  [NNODES + 1];
__device__ int   g_csr [ETOT];
__device__ int   g_bsum[256];
__device__ __nv_bfloat16 g_ah[(size_t)NNODES * HC];
__device__ __nv_bfloat16 g_al[(size_t)NNODES * HC];
__device__ __nv_bfloat16 g_bh[3][131072];
__device__ __nv_bfloat16 g_bl[3][131072];

// ------------------------- helpers ----------------------------------------
__device__ __forceinline__ float lrelu(float v) { return v > 0.f ? v : 0.2f * v; }

__device__ __forceinline__ void mma16816(float* d, const uint32_t* a,
                                         uint32_t b0, uint32_t b1) {
    asm volatile(
        "mma.sync.aligned.m16n8k16.row.col.f32.bf16.bf16.f32 "
        "{%0,%1,%2,%3}, {%4,%5,%6,%7}, {%8,%9}, {%0,%1,%2,%3};"
        : "+f"(d[0]), "+f"(d[1]), "+f"(d[2]), "+f"(d[3])
        : "r"(a[0]), "r"(a[1]), "r"(a[2]), "r"(a[3]), "r"(b0), "r"(b1));
}

__device__ __forceinline__ void cp16(uint32_t dst, const __nv_bfloat16* src,
                                     int srcsz) {
    asm volatile("cp.async.cg.shared.global [%0], [%1], 16, %2;"
                 :: "r"(dst), "l"(src), "r"(srcsz));
}

// ------------------------- prep: all weight splits + deg zero --------------
__global__ void prep_kernel(const float* __restrict__ W1, const float* __restrict__ SW1,
                            const float* __restrict__ W2, const float* __restrict__ SW2,
                            const float* __restrict__ W3, const float* __restrict__ SW3,
                            __nv_bfloat16* __restrict__ bh,
                            __nv_bfloat16* __restrict__ bl,
                            int* __restrict__ deg) {
    const int idx = blockIdx.x * blockDim.x + threadIdx.x;
    if (idx < NNODES) deg[idx] = 0;
    if (idx >= 327680) return;
    int l, which, mi, K;
    const float* src;
    if (idx < 65536)       { l = 0; K = 128; const int r = idx;          which = r >> 15; mi = r & 32767; src = which ? SW1 : W1; }
    else if (idx < 196608) { l = 1; K = 256; const int r = idx - 65536;  which = r >> 16; mi = r & 65535; src = which ? SW2 : W2; }
    else                   { l = 2; K = 256; const int r = idx - 196608; which = r >> 16; mi = r & 65535; src = which ? SW3 : W3; }
    const int k = mi >> 8;
    const int n = mi & 255;
    const float v = src[mi];
    const __nv_bfloat16 h = __float2bfloat16(v);
    const size_t off = (size_t)l * 131072 + (size_t)(which * 256 + n) * K + k;
    bh[off] = h;
    bl[off] = __float2bfloat16(v - __bfloat162float(h));
}

// ------------------------- conv_a ------------------------------------------
__global__ void conv_a_kernel(const float* __restrict__ X,
                              __nv_bfloat16* __restrict__ ah,
                              __nv_bfloat16* __restrict__ al, int total) {
    const int idx = blockIdx.x * blockDim.x + threadIdx.x;
    if (idx >= total) return;
    const float v = X[idx];
    const __nv_bfloat16 h = __float2bfloat16(v);
    ah[idx] = h;
    al[idx] = __float2bfloat16(v - __bfloat162float(h));
}

// ------------------------- fused dual GEMM: cp.async 2-stage pipeline ------
__global__ __launch_bounds__(256, 2)
void gemm_mma_kernel(const __nv_bfloat16* __restrict__ Ah,
                     const __nv_bfloat16* __restrict__ Al,
                     const __nv_bfloat16* __restrict__ Bh,
                     const __nv_bfloat16* __restrict__ Bl,
                     float* __restrict__ Ch,
                     float* __restrict__ Cacc,
                     const float* __restrict__ bias1,
                     const float* __restrict__ bias2,
                     int M, int K) {
    extern __shared__ __nv_bfloat16 smem[];

    const int tid = threadIdx.x;
    const int wid = tid >> 5;
    const int lane = tid & 31;
    const int qr = lane >> 2;
    const int qc = (lane & 3) * 2;
    const int warp_m = (wid >> 2) * 64;
    const int warp_n = (wid & 3) * 32;
    const int m0 = blockIdx.y * 128;
    const int n0 = blockIdx.x * 128;

    float d[4][4][4];
#pragma unroll
    for (int mt = 0; mt < 4; mt++)
#pragma unroll
        for (int nt = 0; nt < 4; nt++)
#pragma unroll
            for (int r = 0; r < 4; r++) d[mt][nt][r] = 0.f;

    const int ar = tid >> 1;             // A/B row 0..127
    const int akh = (tid & 1) * 16;      // k-half: 16 bf16 via 2x16B
    const int aguard = (m0 + ar < M) ? 16 : 0;
    const size_t abase = (size_t)(m0 + ar) * K + akh;
    const size_t bbase = (size_t)(n0 + ar) * K + akh;

    // per-thread smem dst addresses (stage 0); stage 1 = +4*STG elems
    const uint32_t stride_elems = ar * SSTR + akh;
    const uint32_t sAh0 = (uint32_t)__cvta_generic_to_shared(smem + stride_elems);
    const uint32_t sAl0 = sAh0 + STG * 2;
    const uint32_t sBh0 = sAh0 + 2 * STG * 2;
    const uint32_t sBl0 = sAh0 + 3 * STG * 2;
    const uint32_t stageB = 4 * STG * 2;   // bytes per stage

    const int nch = K >> 5;

    // prefetch stage 0 (chunk 0)
    {
        const size_t ao = abase;      // k0 = 0
        const size_t bo = bbase;
        cp16(sAh0,      Ah + ao,     aguard);
        cp16(sAh0 + 16, Ah + ao + 8, aguard);
        cp16(sAl0,      Al + ao,     aguard);
        cp16(sAl0 + 16, Al + ao + 8, aguard);
        cp16(sBh0,      Bh + bo,     16);
        cp16(sBh0 + 16, Bh + bo + 8, 16);
        cp16(sBl0,      Bl + bo,     16);
        cp16(sBl0 + 16, Bl + bo + 8, 16);
        asm volatile("cp.async.commit_group;");
    }

    for (int ch = 0; ch < nch; ch++) {
        if (ch + 1 < nch) {
            const int k1 = (ch + 1) << 5;
            const uint32_t so = ((ch + 1) & 1) * stageB;
            const size_t ao = abase + k1;
            const size_t bo = bbase + k1;
            cp16(sAh0 + so,      Ah + ao,     aguard);
            cp16(sAh0 + so + 16, Ah + ao + 8, aguard);
            cp16(sAl0 + so,      Al + ao,     aguard);
            cp16(sAl0 + so + 16, Al + ao + 8, aguard);
            cp16(sBh0 + so,      Bh + bo,     16);
            cp16(sBh0 + so + 16, Bh + bo + 8, 16);
            cp16(sBl0 + so,      Bl + bo,     16);
            cp16(sBl0 + so + 16, Bl + bo + 8, 16);
            asm volatile("cp.async.commit_group;");
            asm volatile("cp.async.wait_group 1;");
        } else {
            asm volatile("cp.async.wait_group 0;");
        }
        __syncthreads();

        const __nv_bfloat16* cAh = smem + (size_t)(ch & 1) * 4 * STG;
        const __nv_bfloat16* cAl = cAh + STG;
        const __nv_bfloat16* cBh = cAh + 2 * STG;
        const __nv_bfloat16* cBl = cAh + 3 * STG;

#pragma unroll
        for (int ks = 0; ks < 2; ks++) {
            const int kk = ks * 16;
            uint32_t ah[4][4], al[4][4];
#pragma unroll
            for (int mt = 0; mt < 4; mt++) {
                const int r0 = warp_m + mt * 16 + qr;
                ah[mt][0] = *(const uint32_t*)&cAh[r0 * SSTR + kk + qc];
                ah[mt][1] = *(const uint32_t*)&cAh[(r0 + 8) * SSTR + kk + qc];
                ah[mt][2] = *(const uint32_t*)&cAh[r0 * SSTR + kk + 8 + qc];
                ah[mt][3] = *(const uint32_t*)&cAh[(r0 + 8) * SSTR + kk + 8 + qc];
                al[mt][0] = *(const uint32_t*)&cAl[r0 * SSTR + kk + qc];
                al[mt][1] = *(const uint32_t*)&cAl[(r0 + 8) * SSTR + kk + qc];
                al[mt][2] = *(const uint32_t*)&cAl[r0 * SSTR + kk + 8 + qc];
                al[mt][3] = *(const uint32_t*)&cAl[(r0 + 8) * SSTR + kk + 8 + qc];
            }
#pragma unroll
            for (int nt = 0; nt < 4; nt++) {
                const int nr = warp_n + nt * 8 + qr;
                const uint32_t bh0 = *(const uint32_t*)&cBh[nr * SSTR + kk + qc];
                const uint32_t bh1 = *(const uint32_t*)&cBh[nr * SSTR + kk + 8 + qc];
                const uint32_t bl0 = *(const uint32_t*)&cBl[nr * SSTR + kk + qc];
                const uint32_t bl1 = *(const uint32_t*)&cBl[nr * SSTR + kk + 8 + qc];
#pragma unroll
                for (int mt = 0; mt < 4; mt++) {
                    mma16816(d[mt][nt], ah[mt], bh0, bh1);
                    mma16816(d[mt][nt], ah[mt], bl0, bl1);
                    mma16816(d[mt][nt], al[mt], bh0, bh1);
                }
            }
        }
        __syncthreads();
    }

#pragma unroll
    for (int nt = 0; nt < 4; nt++) {
        const int gcol = n0 + warp_n + nt * 8 + qc;
        float* out;
        int col;
        float bv0 = 0.f, bv1 = 0.f;
        if (gcol < 256) {
            out = Ch;  col = gcol;
        } else {
            out = Cacc;  col = gcol - 256;
            bv0 = bias1[col] + bias2[col];
            bv1 = bias1[col + 1] + bias2[col + 1];
        }
#pragma unroll
        for (int mt = 0; mt < 4; mt++) {
            const int r0 = m0 + warp_m + mt * 16 + qr;
            if (r0 < M) {
                float2 v = make_float2(d[mt][nt][0] + bv0, d[mt][nt][1] + bv1);
                *(float2*)&out[(size_t)r0 * HC + col] = v;
            }
            if (r0 + 8 < M) {
                float2 v = make_float2(d[mt][nt][2] + bv0, d[mt][nt][3] + bv1);
                *(float2*)&out[(size_t)(r0 + 8) * HC + col] = v;
            }
        }
    }
}

// ------------------------- CSR build ---------------------------------------
__global__ void hist_kernel(const int* __restrict__ ei, int* __restrict__ deg,
                            int nE, int nTot) {
    const int e = blockIdx.x * blockDim.x + threadIdx.x;
    if (e >= nTot) return;
    const int d = (e < nE) ? ei[nE + e] : (e - nE);
    atomicAdd(&deg[d], 1);
}

__global__ void scan1_kernel(const int* __restrict__ deg, int* __restrict__ bsum,
                             int n) {
    __shared__ int sh[256];
    const int b0 = blockIdx.x * SCAN_BLK;
    const int t = threadIdx.x;
    int s = 0;
    if (b0 + t < n)       s += deg[b0 + t];
    if (b0 + 256 + t < n) s += deg[b0 + 256 + t];
    sh[t] = s;
    __syncthreads();
    for (int off = 128; off > 0; off >>= 1) {
        if (t < off) sh[t] += sh[t + off];
        __syncthreads();
    }
    if (t == 0) bsum[blockIdx.x] = sh[0];
}

__global__ void scan2_kernel(int* __restrict__ bsum, int nb) {
    __shared__ int sh[256];
    const int t = threadIdx.x;
    sh[t] = (t < nb) ? bsum[t] : 0;
    __syncthreads();
    for (int off = 1; off < 256; off <<= 1) {
        const int v = (t >= off) ? sh[t - off] : 0;
        __syncthreads();
        sh[t] += v;
        __syncthreads();
    }
    if (t < nb) bsum[t] = (t == 0) ? 0 : sh[t - 1];
}

__global__ void scan3_kernel(const int* __restrict__ deg,
                             const int* __restrict__ bsum,
                             int* __restrict__ rp, int* __restrict__ cur,
                             int n) {
    __shared__ int sh[SCAN_BLK];
    const int b0 = blockIdx.x * SCAN_BLK;
    const int t = threadIdx.x;
    const int v0 = (b0 + t < n) ? deg[b0 + t] : 0;
    const int v1 = (b0 + 256 + t < n) ? deg[b0 + 256 + t] : 0;
    sh[t] = v0;
    sh[256 + t] = v1;
    __syncthreads();
    for (int off = 1; off < SCAN_BLK; off <<= 1) {
        const int a0 = (t >= off) ? sh[t - off] : 0;
        const int a1 = (t + 256 >= off) ? sh[t + 256 - off] : 0;
        __syncthreads();
        sh[t] += a0;
        sh[256 + t] += a1;
        __syncthreads();
    }
    const int base = bsum[blockIdx.x];
    if (b0 + t < n) {
        const int ex = base + sh[t] - v0;
        rp[b0 + t] = ex;
        cur[b0 + t] = ex;
    }
    if (b0 + 256 + t < n) {
        const int ex = base + sh[256 + t] - v1;
        rp[b0 + 256 + t] = ex;
        cur[b0 + 256 + t] = ex;
    }
    if (blockIdx.x == gridDim.x - 1 && t == 0) rp[n] = base + sh[SCAN_BLK - 1];
}

__global__ void scatter_kernel(const int* __restrict__ ei, int* __restrict__ cur,
                               int* __restrict__ csr, int nE, int nTot) {
    const int e = blockIdx.x * blockDim.x + threadIdx.x;
    if (e >= nTot) return;
    int s, d;
    if (e < nE) { s = ei[e]; d = ei[nE + e]; }
    else        { s = d = e - nE; }
    const int pos = atomicAdd(&cur[d], 1);
    csr[pos] = s;
}

// ------------------------- s/d per node ------------------------------------
__global__ void compute_sd_kernel(const float* __restrict__ gh,
                                  const float* __restrict__ a_src,
                                  const float* __restrict__ a_dst,
                                  float* __restrict__ gs, float* __restrict__ gd,
                                  int n_nodes) {
    const int warp = (blockIdx.x * blockDim.x + threadIdx.x) >> 5;
    const int lane = threadIdx.x & 31;
    if (warp >= n_nodes) return;
    const float* hr = gh + (size_t)warp * HC;
#pragma unroll
    for (int h = 0; h < 4; h++) {
        const float h1 = hr[h * 64 + lane];
        const float h2 = hr[h * 64 + 32 + lane];
        float s = h1 * a_src[h * 64 + lane] + h2 * a_src[h * 64 + 32 + lane];
        float d = h1 * a_dst[h * 64 + lane] + h2 * a_dst[h * 64 + 32 + lane];
#pragma unroll
        for (int off = 16; off > 0; off >>= 1) {
            s += __shfl_down_sync(0xFFFFFFFFu, s, off);
            d += __shfl_down_sync(0xFFFFFFFFu, d, off);
        }
        if (lane == 0) {
            gs[warp * 4 + h] = s;
            gd[warp * 4 + h] = d;
        }
    }
}

// ------------------------- fused softmax + aggregate + skip + ELU ----------
__global__ __launch_bounds__(256)
void node_agg_kernel(const int* __restrict__ rp, const int* __restrict__ csr,
                     const float* __restrict__ gs, const float* __restrict__ gd,
                     const float* __restrict__ gh, const float* __restrict__ gskip,
                     float* __restrict__ xout,
                     __nv_bfloat16* __restrict__ xh,
                     __nv_bfloat16* __restrict__ xl,
                     int nN) {
    const int v = (blockIdx.x * blockDim.x + threadIdx.x) >> 5;
    const int lane = threadIdx.x & 31;
    if (v >= nN) return;

    const int b = rp[v];
    const int e = rp[v + 1];
    const float4 dv = ((const float4*)gd)[v];

    float m0 = -1e30f, m1 = -1e30f, m2 = -1e30f, m3 = -1e30f;
    for (int i = b + lane; i < e; i += 32) {
        const float4 sv = ((const float4*)gs)[csr[i]];
        m0 = fmaxf(m0, lrelu(sv.x + dv.x));
        m1 = fmaxf(m1, lrelu(sv.y + dv.y));
        m2 = fmaxf(m2, lrelu(sv.z + dv.z));
        m3 = fmaxf(m3, lrelu(sv.w + dv.w));
    }
#pragma unroll
    for (int off = 16; off > 0; off >>= 1) {
        m0 = fmaxf(m0, __shfl_xor_sync(0xFFFFFFFFu, m0, off));
        m1 = fmaxf(m1, __shfl_xor_sync(0xFFFFFFFFu, m1, off));
        m2 = fmaxf(m2, __shfl_xor_sync(0xFFFFFFFFu, m2, off));
        m3 = fmaxf(m3, __shfl_xor_sync(0xFFFFFFFFu, m3, off));
    }

    float n0 = 0.f, n1 = 0.f, n2 = 0.f, n3 = 0.f;
    for (int i = b + lane; i < e; i += 32) {
        const float4 sv = ((const float4*)gs)[csr[i]];
        n0 += expf(lrelu(sv.x + dv.x) - m0);
        n1 += expf(lrelu(sv.y + dv.y) - m1);
        n2 += expf(lrelu(sv.z + dv.z) - m2);
        n3 += expf(lrelu(sv.w + dv.w) - m3);
    }
#pragma unroll
    for (int off = 16; off > 0; off >>= 1) {
        n0 += __shfl_xor_sync(0xFFFFFFFFu, n0, off);
        n1 += __shfl_xor_sync(0xFFFFFFFFu, n1, off);
        n2 += __shfl_xor_sync(0xFFFFFFFFu, n2, off);
        n3 += __shfl_xor_sync(0xFFFFFFFFu, n3, off);
    }

    const int h = lane >> 3;
    const float dvh  = (h < 2) ? (h == 0 ? dv.x : dv.y) : (h == 2 ? dv.z : dv.w);
    const float mh   = (h < 2) ? (h == 0 ? m0 : m1) : (h == 2 ? m2 : m3);
    const float dnh  = (h < 2) ? (h == 0 ? n0 : n1) : (h == 2 ? n2 : n3);
    const float invh = 1.f / (dnh + 1e-16f);

    float4 a0 = make_float4(0.f, 0.f, 0.f, 0.f);
    float4 a1 = make_float4(0.f, 0.f, 0.f, 0.f);
#pragma unroll 2
    for (int i = b; i < e; i++) {
        const int s = csr[i];
        const float sval = gs[s * 4 + h];
        const float al = expf(lrelu(sval + dvh) - mh) * invh;
        const float4* hp = (const float4*)(gh + (size_t)s * HC) + lane * 2;
        const float4 v0 = hp[0];
        const float4 v1 = hp[1];
        a0.x = fmaf(v0.x, al, a0.x);  a0.y = fmaf(v0.y, al, a0.y);
        a0.z = fmaf(v0.z, al, a0.z);  a0.w = fmaf(v0.w, al, a0.w);
        a1.x = fmaf(v1.x, al, a1.x);  a1.y = fmaf(v1.y, al, a1.y);
        a1.z = fmaf(v1.z, al, a1.z);  a1.w = fmaf(v1.w, al, a1.w);
    }

    const float4* sp = (const float4*)(gskip + (size_t)v * HC) + lane * 2;
    const float4 s0 = sp[0];
    const float4 s1 = sp[1];
    float4 o0, o1;
    o0.x = a0.x + s0.x;  o0.y = a0.y + s0.y;  o0.z = a0.z + s0.z;  o0.w = a0.w + s0.w;
    o1.x = a1.x + s1.x;  o1.y = a1.y + s1.y;  o1.z = a1.z + s1.z;  o1.w = a1.w + s1.w;
    o0.x = o0.x > 0.f ? o0.x : expm1f(o0.x);
    o0.y = o0.y > 0.f ? o0.y : expm1f(o0.y);
    o0.z = o0.z > 0.f ? o0.z : expm1f(o0.z);
    o0.w = o0.w > 0.f ? o0.w : expm1f(o0.w);
    o1.x = o1.x > 0.f ? o1.x : expm1f(o1.x);
    o1.y = o1.y > 0.f ? o1.y : expm1f(o1.y);
    o1.z = o1.z > 0.f ? o1.z : expm1f(o1.z);
    o1.w = o1.w > 0.f ? o1.w : expm1f(o1.w);
    float4* op = (float4*)(xout + (size_t)v * HC) + lane * 2;
    op[0] = o0;
    op[1] = o1;

    if (xh) {
        __nv_bfloat162 h0 = __floats2bfloat162_rn(o0.x, o0.y);
        __nv_bfloat162 h1 = __floats2bfloat162_rn(o0.z, o0.w);
        __nv_bfloat162 h2 = __floats2bfloat162_rn(o1.x, o1.y);
        __nv_bfloat162 h3 = __floats2bfloat162_rn(o1.z, o1.w);
        __nv_bfloat162 l0 = __floats2bfloat162_rn(o0.x - __low2float(h0), o0.y - __high2float(h0));
        __nv_bfloat162 l1 = __floats2bfloat162_rn(o0.z - __low2float(h1), o0.w - __high2float(h1));
        __nv_bfloat162 l2 = __floats2bfloat162_rn(o1.x - __low2float(h2), o1.y - __high2float(h2));
        __nv_bfloat162 l3 = __floats2bfloat162_rn(o1.z - __low2float(h3), o1.w - __high2float(h3));
        uint4 uh = make_uint4(*(uint32_t*)&h0, *(uint32_t*)&h1, *(uint32_t*)&h2, *(uint32_t*)&h3);
        uint4 ul = make_uint4(*(uint32_t*)&l0, *(uint32_t*)&l1, *(uint32_t*)&l2, *(uint32_t*)&l3);
        *(uint4*)(xh + (size_t)v * HC + lane * 8) = uh;
        *(uint4*)(xl + (size_t)v * HC + lane * 8) = ul;
    }
}

// ---------------------------------------------------------------------------
extern "C" void kernel_launch(void* const* d_in, const int* in_sizes, int n_in,
                              void* d_out, int out_size) {
    const float* x0 = (const float*)d_in[0];
    const int* ei = (const int*)d_in[1];
    const int nE = in_sizes[1] / 2;
    const int nN = NNODES;
    const int nTot = nE + nN;

    const float* W[3]    = {(const float*)d_in[2],  (const float*)d_in[8],  (const float*)d_in[14]};
    const float* ASRC[3] = {(const float*)d_in[3],  (const float*)d_in[9],  (const float*)d_in[15]};
    const float* ADST[3] = {(const float*)d_in[4],  (const float*)d_in[10], (const float*)d_in[16]};
    const float* BB[3]   = {(const float*)d_in[5],  (const float*)d_in[11], (const float*)d_in[17]};
    const float* SW[3]   = {(const float*)d_in[6],  (const float*)d_in[12], (const float*)d_in[18]};
    const float* SB[3]   = {(const float*)d_in[7],  (const float*)d_in[13], (const float*)d_in[19]};
    const int FIN[3] = {128, HC, HC};

    float *ph, *pacc, *px, *ps, *pd;
    int *pdeg, *pcur, *prp, *pcsr, *pbsum;
    __nv_bfloat16 *pbh, *pbl, *pah, *pal;
    cudaGetSymbolAddress((void**)&ph,   g_h);
    cudaGetSymbolAddress((void**)&pacc, g_acc);
    cudaGetSymbolAddress((void**)&px,   g_x);
    cudaGetSymbolAddress((void**)&ps,   g_s);
    cudaGetSymbolAddress((void**)&pd,   g_d);
    cudaGetSymbolAddress((void**)&pdeg, g_deg);
    cudaGetSymbolAddress((void**)&pcur, g_cur);
    cudaGetSymbolAddress((void**)&prp,  g_rp);
    cudaGetSymbolAddress((void**)&pcsr, g_csr);
    cudaGetSymbolAddress((void**)&pbsum,g_bsum);
    cudaGetSymbolAddress((void**)&pbh,  g_bh);
    cudaGetSymbolAddress((void**)&pbl,  g_bl);
    cudaGetSymbolAddress((void**)&pah,  g_ah);
    cudaGetSymbolAddress((void**)&pal,  g_al);

    cudaFuncSetAttribute(gemm_mma_kernel,
                         cudaFuncAttributeMaxDynamicSharedMemorySize, GEMM_SMEM);

    const dim3 gemmGrid(4, (nN + 127) / 128);
    const int eBlocks   = (nTot + 255) / 256;
    const int sdBlocks  = (nN * 32 + 255) / 256;
    const int aggBlocks = (nN * 32 + 255) / 256;
    const int scanBlocks = (nN + SCAN_BLK - 1) / SCAN_BLK;

    // my-launch 0..2: prep, conv_a, hist
    prep_kernel<<<1280, 256>>>(W[0], SW[0], W[1], SW[1], W[2], SW[2],
                               pbh, pbl, pdeg);
    conv_a_kernel<<<(nN * 128 + 255) / 256, 256>>>(x0, pah, pal, nN * 128);
    hist_kernel<<<eBlocks, 256>>>(ei, pdeg, nE, nTot);

    // my-launch 3: layer-1 GEMM (profiled by ncu)
    gemm_mma_kernel<<<gemmGrid, 256, GEMM_SMEM>>>(pah, pal, pbh, pbl, ph, pacc,
                                                  BB[0], SB[0], nN, 128);

    // CSR build
    scan1_kernel<<<scanBlocks, 256>>>(pdeg, pbsum, nN);
    scan2_kernel<<<1, 256>>>(pbsum, scanBlocks);
    scan3_kernel<<<scanBlocks, 256>>>(pdeg, pbsum, prp, pcur, nN);
    scatter_kernel<<<eBlocks, 256>>>(ei, pcur, pcsr, nE, nTot);

    for (int l = 0; l < 3; l++) {
        if (l > 0) {
            __nv_bfloat16* bh = pbh + (size_t)l * 131072;
            __nv_bfloat16* bl = pbl + (size_t)l * 131072;
            gemm_mma_kernel<<<gemmGrid, 256, GEMM_SMEM>>>(pah, pal, bh, bl, ph, pacc,
                                                          BB[l], SB[l], nN, FIN[l]);
        }
        compute_sd_kernel<<<sdBlocks, 256>>>(ph, ASRC[l], ADST[l], ps, pd, nN);
        float* xout = (l == 2) ? (float*)d_out : px;
        __nv_bfloat16* xh = (l == 2) ? nullptr : pah;
        __nv_bfloat16* xl = (l == 2) ? nullptr : pal;
        node_agg_kernel<<<aggBlocks, 256>>>(prp, pcsr, ps, pd, ph, pacc,
                                            xout, xh, xl, nN);
    }
}

// round 11
// speedup vs baseline: 1.4434x; 1.1847x over previous
#include <cuda_runtime.h>
#include <cuda_fp16.h>
#include <cuda_bf16.h>
#include <cstdint>

// ---------------------------------------------------------------------------
// GATEncoder: 3 layers of (GATConv + linear skip + ELU)
// N=50000, E=800000 (+N self loops), IN=128, H=4, C=64, HC=256
// Round 11: fp16 2-product GEMM (A single fp16, B split fp16 hi/lo).
//           Error model: ~2.8e-4 rel (vs 1e-3 threshold). 2/3 MMA work,
//           2/3 smem fragment traffic vs bf16 3-product.
// ---------------------------------------------------------------------------

#define NNODES 50000
#define NEDGES 800000
#define ETOT   (NEDGES + NNODES)
#define HC     256
#define SCAN_BLK 512
#define SSTR 40
#define STG  (128 * SSTR)              // elems per matrix per stage
#define STAGE_B (3 * STG * 2)          // bytes per stage: A, Bh, Bl
#define GEMM_SMEM (2 * STAGE_B)

// ------------------------- static device scratch ---------------------------
__device__ float g_h   [(size_t)NNODES * HC];
__device__ float g_acc [(size_t)NNODES * HC];
__device__ float g_x   [(size_t)NNODES * HC];
__device__ float g_s   [(size_t)NNODES * 4];
__device__ float g_d   [(size_t)NNODES * 4];
__device__ int   g_deg [NNODES];
__device__ int   g_cur [NNODES];
__device__ int   g_rp  [NNODES + 1];
__device__ int   g_csr [ETOT];
__device__ int   g_bsum[256];
__device__ __half g_a16[(size_t)NNODES * HC];    // GEMM input, single fp16
__device__ __half g_bh [3][131072];              // W fused [512,K] fp16 hi
__device__ __half g_bl [3][131072];              // fp16 lo (residual)

// ------------------------- helpers ----------------------------------------
__device__ __forceinline__ float lrelu(float v) { return v > 0.f ? v : 0.2f * v; }

__device__ __forceinline__ void mma16816(float* d, const uint32_t* a,
                                         uint32_t b0, uint32_t b1) {
    asm volatile(
        "mma.sync.aligned.m16n8k16.row.col.f32.f16.f16.f32 "
        "{%0,%1,%2,%3}, {%4,%5,%6,%7}, {%8,%9}, {%0,%1,%2,%3};"
        : "+f"(d[0]), "+f"(d[1]), "+f"(d[2]), "+f"(d[3])
        : "r"(a[0]), "r"(a[1]), "r"(a[2]), "r"(a[3]), "r"(b0), "r"(b1));
}

__device__ __forceinline__ void cp16(uint32_t dst, const __half* src, int srcsz) {
    asm volatile("cp.async.cg.shared.global [%0], [%1], 16, %2;"
                 :: "r"(dst), "l"(src), "r"(srcsz));
}

// ------------------------- prep: weight fp16 splits + deg zero -------------
__global__ void prep_kernel(const float* __restrict__ W1, const float* __restrict__ SW1,
                            const float* __restrict__ W2, const float* __restrict__ SW2,
                            const float* __restrict__ W3, const float* __restrict__ SW3,
                            __half* __restrict__ bh, __half* __restrict__ bl,
                            int* __restrict__ deg) {
    const int idx = blockIdx.x * blockDim.x + threadIdx.x;
    if (idx < NNODES) deg[idx] = 0;
    if (idx >= 327680) return;
    int l, which, mi, K;
    const float* src;
    if (idx < 65536)       { l = 0; K = 128; const int r = idx;          which = r >> 15; mi = r & 32767; src = which ? SW1 : W1; }
    else if (idx < 196608) { l = 1; K = 256; const int r = idx - 65536;  which = r >> 16; mi = r & 65535; src = which ? SW2 : W2; }
    else                   { l = 2; K = 256; const int r = idx - 196608; which = r >> 16; mi = r & 65535; src = which ? SW3 : W3; }
    const int k = mi >> 8;
    const int n = mi & 255;
    const float v = src[mi];
    const __half h = __float2half_rn(v);
    const size_t off = (size_t)l * 131072 + (size_t)(which * 256 + n) * K + k;
    bh[off] = h;
    bl[off] = __float2half_rn(v - __half2float(h));
}

// ------------------------- conv_a: fp32 -> fp16 (layer-1 input) ------------
__global__ void conv_a_kernel(const float* __restrict__ X,
                              __half* __restrict__ a16, int total) {
    const int idx = blockIdx.x * blockDim.x + threadIdx.x;
    if (idx >= total) return;
    a16[idx] = __float2half_rn(X[idx]);
}

// ------------------------- fused dual GEMM: fp16 2-product, cp.async -------
__global__ __launch_bounds__(256, 2)
void gemm_mma_kernel(const __half* __restrict__ A,
                     const __half* __restrict__ Bh,
                     const __half* __restrict__ Bl,
                     float* __restrict__ Ch,
                     float* __restrict__ Cacc,
                     const float* __restrict__ bias1,
                     const float* __restrict__ bias2,
                     int M, int K) {
    extern __shared__ __half smem[];

    const int tid = threadIdx.x;
    const int wid = tid >> 5;
    const int lane = tid & 31;
    const int qr = lane >> 2;
    const int qc = (lane & 3) * 2;
    const int warp_m = (wid >> 2) * 64;
    const int warp_n = (wid & 3) * 32;
    const int m0 = blockIdx.y * 128;
    const int n0 = blockIdx.x * 128;

    float d[4][4][4];
#pragma unroll
    for (int mt = 0; mt < 4; mt++)
#pragma unroll
        for (int nt = 0; nt < 4; nt++)
#pragma unroll
            for (int r = 0; r < 4; r++) d[mt][nt][r] = 0.f;

    const int ar = tid >> 1;             // row 0..127
    const int akh = (tid & 1) * 16;      // k-half: 16 halves via 2x16B
    const int aguard = (m0 + ar < M) ? 16 : 0;
    const size_t abase = (size_t)(m0 + ar) * K + akh;
    const size_t bbase = (size_t)(n0 + ar) * K + akh;

    const uint32_t sA0 = (uint32_t)__cvta_generic_to_shared(smem + ar * SSTR + akh);
    const uint32_t sBh0 = sA0 + STG * 2;
    const uint32_t sBl0 = sA0 + 2 * STG * 2;

    const int nch = K >> 5;

    // prefetch chunk 0 into stage 0
    {
        cp16(sA0,       A + abase,      aguard);
        cp16(sA0 + 16,  A + abase + 8,  aguard);
        cp16(sBh0,      Bh + bbase,     16);
        cp16(sBh0 + 16, Bh + bbase + 8, 16);
        cp16(sBl0,      Bl + bbase,     16);
        cp16(sBl0 + 16, Bl + bbase + 8, 16);
        asm volatile("cp.async.commit_group;");
    }

    for (int ch = 0; ch < nch; ch++) {
        if (ch + 1 < nch) {
            const int k1 = (ch + 1) << 5;
            const uint32_t so = ((ch + 1) & 1) * STAGE_B;
            cp16(sA0 + so,       A + abase + k1,      aguard);
            cp16(sA0 + so + 16,  A + abase + k1 + 8,  aguard);
            cp16(sBh0 + so,      Bh + bbase + k1,     16);
            cp16(sBh0 + so + 16, Bh + bbase + k1 + 8, 16);
            cp16(sBl0 + so,      Bl + bbase + k1,     16);
            cp16(sBl0 + so + 16, Bl + bbase + k1 + 8, 16);
            asm volatile("cp.async.commit_group;");
            asm volatile("cp.async.wait_group 1;");
        } else {
            asm volatile("cp.async.wait_group 0;");
        }
        __syncthreads();

        const __half* cA  = smem + (size_t)(ch & 1) * 3 * STG;
        const __half* cBh = cA + STG;
        const __half* cBl = cA + 2 * STG;

#pragma unroll
        for (int ks = 0; ks < 2; ks++) {
            const int kk = ks * 16;
            uint32_t ah[4][4];
#pragma unroll
            for (int mt = 0; mt < 4; mt++) {
                const int r0 = warp_m + mt * 16 + qr;
                ah[mt][0] = *(const uint32_t*)&cA[r0 * SSTR + kk + qc];
                ah[mt][1] = *(const uint32_t*)&cA[(r0 + 8) * SSTR + kk + qc];
                ah[mt][2] = *(const uint32_t*)&cA[r0 * SSTR + kk + 8 + qc];
                ah[mt][3] = *(const uint32_t*)&cA[(r0 + 8) * SSTR + kk + 8 + qc];
            }
#pragma unroll
            for (int nt = 0; nt < 4; nt++) {
                const int nr = warp_n + nt * 8 + qr;
                const uint32_t bh0 = *(const uint32_t*)&cBh[nr * SSTR + kk + qc];
                const uint32_t bh1 = *(const uint32_t*)&cBh[nr * SSTR + kk + 8 + qc];
                const uint32_t bl0 = *(const uint32_t*)&cBl[nr * SSTR + kk + qc];
                const uint32_t bl1 = *(const uint32_t*)&cBl[nr * SSTR + kk + 8 + qc];
#pragma unroll
                for (int mt = 0; mt < 4; mt++) {
                    mma16816(d[mt][nt], ah[mt], bh0, bh1);
                    mma16816(d[mt][nt], ah[mt], bl0, bl1);
                }
            }
        }
        __syncthreads();
    }

#pragma unroll
    for (int nt = 0; nt < 4; nt++) {
        const int gcol = n0 + warp_n + nt * 8 + qc;
        float* out;
        int col;
        float bv0 = 0.f, bv1 = 0.f;
        if (gcol < 256) {
            out = Ch;  col = gcol;
        } else {
            out = Cacc;  col = gcol - 256;
            bv0 = bias1[col] + bias2[col];
            bv1 = bias1[col + 1] + bias2[col + 1];
        }
#pragma unroll
        for (int mt = 0; mt < 4; mt++) {
            const int r0 = m0 + warp_m + mt * 16 + qr;
            if (r0 < M) {
                float2 v = make_float2(d[mt][nt][0] + bv0, d[mt][nt][1] + bv1);
                *(float2*)&out[(size_t)r0 * HC + col] = v;
            }
            if (r0 + 8 < M) {
                float2 v = make_float2(d[mt][nt][2] + bv0, d[mt][nt][3] + bv1);
                *(float2*)&out[(size_t)(r0 + 8) * HC + col] = v;
            }
        }
    }
}

// ------------------------- CSR build ---------------------------------------
__global__ void hist_kernel(const int* __restrict__ ei, int* __restrict__ deg,
                            int nE, int nTot) {
    const int e = blockIdx.x * blockDim.x + threadIdx.x;
    if (e >= nTot) return;
    const int d = (e < nE) ? ei[nE + e] : (e - nE);
    atomicAdd(&deg[d], 1);
}

__global__ void scan1_kernel(const int* __restrict__ deg, int* __restrict__ bsum,
                             int n) {
    __shared__ int sh[256];
    const int b0 = blockIdx.x * SCAN_BLK;
    const int t = threadIdx.x;
    int s = 0;
    if (b0 + t < n)       s += deg[b0 + t];
    if (b0 + 256 + t < n) s += deg[b0 + 256 + t];
    sh[t] = s;
    __syncthreads();
    for (int off = 128; off > 0; off >>= 1) {
        if (t < off) sh[t] += sh[t + off];
        __syncthreads();
    }
    if (t == 0) bsum[blockIdx.x] = sh[0];
}

__global__ void scan2_kernel(int* __restrict__ bsum, int nb) {
    __shared__ int sh[256];
    const int t = threadIdx.x;
    sh[t] = (t < nb) ? bsum[t] : 0;
    __syncthreads();
    for (int off = 1; off < 256; off <<= 1) {
        const int v = (t >= off) ? sh[t - off] : 0;
        __syncthreads();
        sh[t] += v;
        __syncthreads();
    }
    if (t < nb) bsum[t] = (t == 0) ? 0 : sh[t - 1];
}

__global__ void scan3_kernel(const int* __restrict__ deg,
                             const int* __restrict__ bsum,
                             int* __restrict__ rp, int* __restrict__ cur,
                             int n) {
    __shared__ int sh[SCAN_BLK];
    const int b0 = blockIdx.x * SCAN_BLK;
    const int t = threadIdx.x;
    const int v0 = (b0 + t < n) ? deg[b0 + t] : 0;
    const int v1 = (b0 + 256 + t < n) ? deg[b0 + 256 + t] : 0;
    sh[t] = v0;
    sh[256 + t] = v1;
    __syncthreads();
    for (int off = 1; off < SCAN_BLK; off <<= 1) {
        const int a0 = (t >= off) ? sh[t - off] : 0;
        const int a1 = (t + 256 >= off) ? sh[t + 256 - off] : 0;
        __syncthreads();
        sh[t] += a0;
        sh[256 + t] += a1;
        __syncthreads();
    }
    const int base = bsum[blockIdx.x];
    if (b0 + t < n) {
        const int ex = base + sh[t] - v0;
        rp[b0 + t] = ex;
        cur[b0 + t] = ex;
    }
    if (b0 + 256 + t < n) {
        const int ex = base + sh[256 + t] - v1;
        rp[b0 + 256 + t] = ex;
        cur[b0 + 256 + t] = ex;
    }
    if (blockIdx.x == gridDim.x - 1 && t == 0) rp[n] = base + sh[SCAN_BLK - 1];
}

__global__ void scatter_kernel(const int* __restrict__ ei, int* __restrict__ cur,
                               int* __restrict__ csr, int nE, int nTot) {
    const int e = blockIdx.x * blockDim.x + threadIdx.x;
    if (e >= nTot) return;
    int s, d;
    if (e < nE) { s = ei[e]; d = ei[nE + e]; }
    else        { s = d = e - nE; }
    const int pos = atomicAdd(&cur[d], 1);
    csr[pos] = s;
}

// ------------------------- s/d per node ------------------------------------
__global__ void compute_sd_kernel(const float* __restrict__ gh,
                                  const float* __restrict__ a_src,
                                  const float* __restrict__ a_dst,
                                  float* __restrict__ gs, float* __restrict__ gd,
                                  int n_nodes) {
    const int warp = (blockIdx.x * blockDim.x + threadIdx.x) >> 5;
    const int lane = threadIdx.x & 31;
    if (warp >= n_nodes) return;
    const float* hr = gh + (size_t)warp * HC;
#pragma unroll
    for (int h = 0; h < 4; h++) {
        const float h1 = hr[h * 64 + lane];
        const float h2 = hr[h * 64 + 32 + lane];
        float s = h1 * a_src[h * 64 + lane] + h2 * a_src[h * 64 + 32 + lane];
        float d = h1 * a_dst[h * 64 + lane] + h2 * a_dst[h * 64 + 32 + lane];
#pragma unroll
        for (int off = 16; off > 0; off >>= 1) {
            s += __shfl_down_sync(0xFFFFFFFFu, s, off);
            d += __shfl_down_sync(0xFFFFFFFFu, d, off);
        }
        if (lane == 0) {
            gs[warp * 4 + h] = s;
            gd[warp * 4 + h] = d;
        }
    }
}

// ------------------------- fused softmax + aggregate + skip + ELU ----------
__global__ __launch_bounds__(256)
void node_agg_kernel(const int* __restrict__ rp, const int* __restrict__ csr,
                     const float* __restrict__ gs, const float* __restrict__ gd,
                     const float* __restrict__ gh, const float* __restrict__ gskip,
                     float* __restrict__ xout,
                     __half* __restrict__ x16,
                     int nN) {
    const int v = (blockIdx.x * blockDim.x + threadIdx.x) >> 5;
    const int lane = threadIdx.x & 31;
    if (v >= nN) return;

    const int b = rp[v];
    const int e = rp[v + 1];
    const float4 dv = ((const float4*)gd)[v];

    float m0 = -1e30f, m1 = -1e30f, m2 = -1e30f, m3 = -1e30f;
    for (int i = b + lane; i < e; i += 32) {
        const float4 sv = ((const float4*)gs)[csr[i]];
        m0 = fmaxf(m0, lrelu(sv.x + dv.x));
        m1 = fmaxf(m1, lrelu(sv.y + dv.y));
        m2 = fmaxf(m2, lrelu(sv.z + dv.z));
        m3 = fmaxf(m3, lrelu(sv.w + dv.w));
    }
#pragma unroll
    for (int off = 16; off > 0; off >>= 1) {
        m0 = fmaxf(m0, __shfl_xor_sync(0xFFFFFFFFu, m0, off));
        m1 = fmaxf(m1, __shfl_xor_sync(0xFFFFFFFFu, m1, off));
        m2 = fmaxf(m2, __shfl_xor_sync(0xFFFFFFFFu, m2, off));
        m3 = fmaxf(m3, __shfl_xor_sync(0xFFFFFFFFu, m3, off));
    }

    float n0 = 0.f, n1 = 0.f, n2 = 0.f, n3 = 0.f;
    for (int i = b + lane; i < e; i += 32) {
        const float4 sv = ((const float4*)gs)[csr[i]];
        n0 += expf(lrelu(sv.x + dv.x) - m0);
        n1 += expf(lrelu(sv.y + dv.y) - m1);
        n2 += expf(lrelu(sv.z + dv.z) - m2);
        n3 += expf(lrelu(sv.w + dv.w) - m3);
    }
#pragma unroll
    for (int off = 16; off > 0; off >>= 1) {
        n0 += __shfl_xor_sync(0xFFFFFFFFu, n0, off);
        n1 += __shfl_xor_sync(0xFFFFFFFFu, n1, off);
        n2 += __shfl_xor_sync(0xFFFFFFFFu, n2, off);
        n3 += __shfl_xor_sync(0xFFFFFFFFu, n3, off);
    }

    const int h = lane >> 3;
    const float dvh  = (h < 2) ? (h == 0 ? dv.x : dv.y) : (h == 2 ? dv.z : dv.w);
    const float mh   = (h < 2) ? (h == 0 ? m0 : m1) : (h == 2 ? m2 : m3);
    const float dnh  = (h < 2) ? (h == 0 ? n0 : n1) : (h == 2 ? n2 : n3);
    const float invh = 1.f / (dnh + 1e-16f);

    float4 a0 = make_float4(0.f, 0.f, 0.f, 0.f);
    float4 a1 = make_float4(0.f, 0.f, 0.f, 0.f);
#pragma unroll 2
    for (int i = b; i < e; i++) {
        const int s = csr[i];
        const float sval = gs[s * 4 + h];
        const float al = expf(lrelu(sval + dvh) - mh) * invh;
        const float4* hp = (const float4*)(gh + (size_t)s * HC) + lane * 2;
        const float4 v0 = hp[0];
        const float4 v1 = hp[1];
        a0.x = fmaf(v0.x, al, a0.x);  a0.y = fmaf(v0.y, al, a0.y);
        a0.z = fmaf(v0.z, al, a0.z);  a0.w = fmaf(v0.w, al, a0.w);
        a1.x = fmaf(v1.x, al, a1.x);  a1.y = fmaf(v1.y, al, a1.y);
        a1.z = fmaf(v1.z, al, a1.z);  a1.w = fmaf(v1.w, al, a1.w);
    }

    const float4* sp = (const float4*)(gskip + (size_t)v * HC) + lane * 2;
    const float4 s0 = sp[0];
    const float4 s1 = sp[1];
    float4 o0, o1;
    o0.x = a0.x + s0.x;  o0.y = a0.y + s0.y;  o0.z = a0.z + s0.z;  o0.w = a0.w + s0.w;
    o1.x = a1.x + s1.x;  o1.y = a1.y + s1.y;  o1.z = a1.z + s1.z;  o1.w = a1.w + s1.w;
    o0.x = o0.x > 0.f ? o0.x : expm1f(o0.x);
    o0.y = o0.y > 0.f ? o0.y : expm1f(o0.y);
    o0.z = o0.z > 0.f ? o0.z : expm1f(o0.z);
    o0.w = o0.w > 0.f ? o0.w : expm1f(o0.w);
    o1.x = o1.x > 0.f ? o1.x : expm1f(o1.x);
    o1.y = o1.y > 0.f ? o1.y : expm1f(o1.y);
    o1.z = o1.z > 0.f ? o1.z : expm1f(o1.z);
    o1.w = o1.w > 0.f ? o1.w : expm1f(o1.w);
    float4* op = (float4*)(xout + (size_t)v * HC) + lane * 2;
    op[0] = o0;
    op[1] = o1;

    if (x16) {
        __half2 p0 = __floats2half2_rn(o0.x, o0.y);
        __half2 p1 = __floats2half2_rn(o0.z, o0.w);
        __half2 p2 = __floats2half2_rn(o1.x, o1.y);
        __half2 p3 = __floats2half2_rn(o1.z, o1.w);
        uint4 u = make_uint4(*(uint32_t*)&p0, *(uint32_t*)&p1,
                             *(uint32_t*)&p2, *(uint32_t*)&p3);
        *(uint4*)(x16 + (size_t)v * HC + lane * 8) = u;
    }
}

// ---------------------------------------------------------------------------
extern "C" void kernel_launch(void* const* d_in, const int* in_sizes, int n_in,
                              void* d_out, int out_size) {
    const float* x0 = (const float*)d_in[0];
    const int* ei = (const int*)d_in[1];
    const int nE = in_sizes[1] / 2;
    const int nN = NNODES;
    const int nTot = nE + nN;

    const float* W[3]    = {(const float*)d_in[2],  (const float*)d_in[8],  (const float*)d_in[14]};
    const float* ASRC[3] = {(const float*)d_in[3],  (const float*)d_in[9],  (const float*)d_in[15]};
    const float* ADST[3] = {(const float*)d_in[4],  (const float*)d_in[10], (const float*)d_in[16]};
    const float* BB[3]   = {(const float*)d_in[5],  (const float*)d_in[11], (const float*)d_in[17]};
    const float* SW[3]   = {(const float*)d_in[6],  (const float*)d_in[12], (const float*)d_in[18]};
    const float* SB[3]   = {(const float*)d_in[7],  (const float*)d_in[13], (const float*)d_in[19]};
    const int FIN[3] = {128, HC, HC};

    float *ph, *pacc, *px, *ps, *pd;
    int *pdeg, *pcur, *prp, *pcsr, *pbsum;
    __half *pbh, *pbl, *pa16;
    cudaGetSymbolAddress((void**)&ph,   g_h);
    cudaGetSymbolAddress((void**)&pacc, g_acc);
    cudaGetSymbolAddress((void**)&px,   g_x);
    cudaGetSymbolAddress((void**)&ps,   g_s);
    cudaGetSymbolAddress((void**)&pd,   g_d);
    cudaGetSymbolAddress((void**)&pdeg, g_deg);
    cudaGetSymbolAddress((void**)&pcur, g_cur);
    cudaGetSymbolAddress((void**)&prp,  g_rp);
    cudaGetSymbolAddress((void**)&pcsr, g_csr);
    cudaGetSymbolAddress((void**)&pbsum,g_bsum);
    cudaGetSymbolAddress((void**)&pbh,  g_bh);
    cudaGetSymbolAddress((void**)&pbl,  g_bl);
    cudaGetSymbolAddress((void**)&pa16, g_a16);

    cudaFuncSetAttribute(gemm_mma_kernel,
                         cudaFuncAttributeMaxDynamicSharedMemorySize, GEMM_SMEM);

    const dim3 gemmGrid(4, (nN + 127) / 128);
    const int eBlocks   = (nTot + 255) / 256;
    const int sdBlocks  = (nN * 32 + 255) / 256;
    const int aggBlocks = (nN * 32 + 255) / 256;
    const int scanBlocks = (nN + SCAN_BLK - 1) / SCAN_BLK;

    // my-launch 0..2: prep, conv_a, hist
    prep_kernel<<<1280, 256>>>(W[0], SW[0], W[1], SW[1], W[2], SW[2],
                               pbh, pbl, pdeg);
    conv_a_kernel<<<(nN * 128 + 255) / 256, 256>>>(x0, pa16, nN * 128);
    hist_kernel<<<eBlocks, 256>>>(ei, pdeg, nE, nTot);

    // my-launch 3: layer-1 GEMM (profiled by ncu)
    gemm_mma_kernel<<<gemmGrid, 256, GEMM_SMEM>>>(pa16, pbh, pbl, ph, pacc,
                                                  BB[0], SB[0], nN, 128);

    // CSR build
    scan1_kernel<<<scanBlocks, 256>>>(pdeg, pbsum, nN);
    scan2_kernel<<<1, 256>>>(pbsum, scanBlocks);
    scan3_kernel<<<scanBlocks, 256>>>(pdeg, pbsum, prp, pcur, nN);
    scatter_kernel<<<eBlocks, 256>>>(ei, pcur, pcsr, nE, nTot);

    for (int l = 0; l < 3; l++) {
        if (l > 0) {
            __half* bh = pbh + (size_t)l * 131072;
            __half* bl = pbl + (size_t)l * 131072;
            gemm_mma_kernel<<<gemmGrid, 256, GEMM_SMEM>>>(pa16, bh, bl, ph, pacc,
                                                          BB[l], SB[l], nN, FIN[l]);
        }
        compute_sd_kernel<<<sdBlocks, 256>>>(ph, ASRC[l], ADST[l], ps, pd, nN);
        float* xout = (l == 2) ? (float*)d_out : px;
        __half* x16 = (l == 2) ? nullptr : pa16;
        node_agg_kernel<<<aggBlocks, 256>>>(prp, pcsr, ps, pd, ph, pacc,
                                            xout, x16, nN);
    }
}

// round 12
// speedup vs baseline: 1.5313x; 1.0609x over previous
#include <cuda_runtime.h>
#include <cuda_fp16.h>
#include <cstdint>

// ---------------------------------------------------------------------------
// GATEncoder: 3 layers of (GATConv + linear skip + ELU)
// N=50000, E=800000 (+N self loops), IN=128, H=4, C=64, HC=256
// Round 12: h stored fp16 (halves gather/write traffic in GEMM epilogue,
//           compute_sd, node_agg pass-3). fp16 2-product GEMM unchanged.
// ---------------------------------------------------------------------------

#define NNODES 50000
#define NEDGES 800000
#define ETOT   (NEDGES + NNODES)
#define HC     256
#define SCAN_BLK 512
#define SSTR 40
#define STG  (128 * SSTR)
#define STAGE_B (3 * STG * 2)
#define GEMM_SMEM (2 * STAGE_B)

// ------------------------- static device scratch ---------------------------
__device__ __half g_h16[(size_t)NNODES * HC];    // x @ W  (fp16)
__device__ float g_acc [(size_t)NNODES * HC];    // skip + biases (fp32)
__device__ float g_x   [(size_t)NNODES * HC];
__device__ float g_s   [(size_t)NNODES * 4];
__device__ float g_d   [(size_t)NNODES * 4];
__device__ int   g_deg [NNODES];
__device__ int   g_cur [NNODES];
__device__ int   g_rp  [NNODES + 1];
__device__ int   g_csr [ETOT];
__device__ int   g_bsum[256];
__device__ __half g_a16[(size_t)NNODES * HC];    // GEMM input (fp16)
__device__ __half g_bh [3][131072];
__device__ __half g_bl [3][131072];

// ------------------------- helpers ----------------------------------------
__device__ __forceinline__ float lrelu(float v) { return v > 0.f ? v : 0.2f * v; }

__device__ __forceinline__ void mma16816(float* d, const uint32_t* a,
                                         uint32_t b0, uint32_t b1) {
    asm volatile(
        "mma.sync.aligned.m16n8k16.row.col.f32.f16.f16.f32 "
        "{%0,%1,%2,%3}, {%4,%5,%6,%7}, {%8,%9}, {%0,%1,%2,%3};"
        : "+f"(d[0]), "+f"(d[1]), "+f"(d[2]), "+f"(d[3])
        : "r"(a[0]), "r"(a[1]), "r"(a[2]), "r"(a[3]), "r"(b0), "r"(b1));
}

__device__ __forceinline__ void cp16(uint32_t dst, const __half* src, int srcsz) {
    asm volatile("cp.async.cg.shared.global [%0], [%1], 16, %2;"
                 :: "r"(dst), "l"(src), "r"(srcsz));
}

// ------------------------- prep ---------------------------------------------
__global__ void prep_kernel(const float* __restrict__ W1, const float* __restrict__ SW1,
                            const float* __restrict__ W2, const float* __restrict__ SW2,
                            const float* __restrict__ W3, const float* __restrict__ SW3,
                            __half* __restrict__ bh, __half* __restrict__ bl,
                            int* __restrict__ deg) {
    const int idx = blockIdx.x * blockDim.x + threadIdx.x;
    if (idx < NNODES) deg[idx] = 0;
    if (idx >= 327680) return;
    int l, which, mi, K;
    const float* src;
    if (idx < 65536)       { l = 0; K = 128; const int r = idx;          which = r >> 15; mi = r & 32767; src = which ? SW1 : W1; }
    else if (idx < 196608) { l = 1; K = 256; const int r = idx - 65536;  which = r >> 16; mi = r & 65535; src = which ? SW2 : W2; }
    else                   { l = 2; K = 256; const int r = idx - 196608; which = r >> 16; mi = r & 65535; src = which ? SW3 : W3; }
    const int k = mi >> 8;
    const int n = mi & 255;
    const float v = src[mi];
    const __half h = __float2half_rn(v);
    const size_t off = (size_t)l * 131072 + (size_t)(which * 256 + n) * K + k;
    bh[off] = h;
    bl[off] = __float2half_rn(v - __half2float(h));
}

// ------------------------- conv_a -------------------------------------------
__global__ void conv_a_kernel(const float* __restrict__ X,
                              __half* __restrict__ a16, int total) {
    const int idx = blockIdx.x * blockDim.x + threadIdx.x;
    if (idx >= total) return;
    a16[idx] = __float2half_rn(X[idx]);
}

// ------------------------- fused dual GEMM (fp16 2-product, cp.async) ------
// Ch (cols 0..255) -> fp16 h buffer; Cacc (cols 256..511) -> fp32 + biases
__global__ __launch_bounds__(256, 2)
void gemm_mma_kernel(const __half* __restrict__ A,
                     const __half* __restrict__ Bh,
                     const __half* __restrict__ Bl,
                     __half* __restrict__ Ch16,
                     float* __restrict__ Cacc,
                     const float* __restrict__ bias1,
                     const float* __restrict__ bias2,
                     int M, int K) {
    extern __shared__ __half smem[];

    const int tid = threadIdx.x;
    const int wid = tid >> 5;
    const int lane = tid & 31;
    const int qr = lane >> 2;
    const int qc = (lane & 3) * 2;
    const int warp_m = (wid >> 2) * 64;
    const int warp_n = (wid & 3) * 32;
    const int m0 = blockIdx.y * 128;
    const int n0 = blockIdx.x * 128;

    float d[4][4][4];
#pragma unroll
    for (int mt = 0; mt < 4; mt++)
#pragma unroll
        for (int nt = 0; nt < 4; nt++)
#pragma unroll
            for (int r = 0; r < 4; r++) d[mt][nt][r] = 0.f;

    const int ar = tid >> 1;
    const int akh = (tid & 1) * 16;
    const int aguard = (m0 + ar < M) ? 16 : 0;
    const size_t abase = (size_t)(m0 + ar) * K + akh;
    const size_t bbase = (size_t)(n0 + ar) * K + akh;

    const uint32_t sA0 = (uint32_t)__cvta_generic_to_shared(smem + ar * SSTR + akh);
    const uint32_t sBh0 = sA0 + STG * 2;
    const uint32_t sBl0 = sA0 + 2 * STG * 2;

    const int nch = K >> 5;

    {
        cp16(sA0,       A + abase,      aguard);
        cp16(sA0 + 16,  A + abase + 8,  aguard);
        cp16(sBh0,      Bh + bbase,     16);
        cp16(sBh0 + 16, Bh + bbase + 8, 16);
        cp16(sBl0,      Bl + bbase,     16);
        cp16(sBl0 + 16, Bl + bbase + 8, 16);
        asm volatile("cp.async.commit_group;");
    }

    for (int ch = 0; ch < nch; ch++) {
        if (ch + 1 < nch) {
            const int k1 = (ch + 1) << 5;
            const uint32_t so = ((ch + 1) & 1) * STAGE_B;
            cp16(sA0 + so,       A + abase + k1,      aguard);
            cp16(sA0 + so + 16,  A + abase + k1 + 8,  aguard);
            cp16(sBh0 + so,      Bh + bbase + k1,     16);
            cp16(sBh0 + so + 16, Bh + bbase + k1 + 8, 16);
            cp16(sBl0 + so,      Bl + bbase + k1,     16);
            cp16(sBl0 + so + 16, Bl + bbase + k1 + 8, 16);
            asm volatile("cp.async.commit_group;");
            asm volatile("cp.async.wait_group 1;");
        } else {
            asm volatile("cp.async.wait_group 0;");
        }
        __syncthreads();

        const __half* cA  = smem + (size_t)(ch & 1) * 3 * STG;
        const __half* cBh = cA + STG;
        const __half* cBl = cA + 2 * STG;

#pragma unroll
        for (int ks = 0; ks < 2; ks++) {
            const int kk = ks * 16;
            uint32_t ah[4][4];
#pragma unroll
            for (int mt = 0; mt < 4; mt++) {
                const int r0 = warp_m + mt * 16 + qr;
                ah[mt][0] = *(const uint32_t*)&cA[r0 * SSTR + kk + qc];
                ah[mt][1] = *(const uint32_t*)&cA[(r0 + 8) * SSTR + kk + qc];
                ah[mt][2] = *(const uint32_t*)&cA[r0 * SSTR + kk + 8 + qc];
                ah[mt][3] = *(const uint32_t*)&cA[(r0 + 8) * SSTR + kk + 8 + qc];
            }
#pragma unroll
            for (int nt = 0; nt < 4; nt++) {
                const int nr = warp_n + nt * 8 + qr;
                const uint32_t bh0 = *(const uint32_t*)&cBh[nr * SSTR + kk + qc];
                const uint32_t bh1 = *(const uint32_t*)&cBh[nr * SSTR + kk + 8 + qc];
                const uint32_t bl0 = *(const uint32_t*)&cBl[nr * SSTR + kk + qc];
                const uint32_t bl1 = *(const uint32_t*)&cBl[nr * SSTR + kk + 8 + qc];
#pragma unroll
                for (int mt = 0; mt < 4; mt++) {
                    mma16816(d[mt][nt], ah[mt], bh0, bh1);
                    mma16816(d[mt][nt], ah[mt], bl0, bl1);
                }
            }
        }
        __syncthreads();
    }

#pragma unroll
    for (int nt = 0; nt < 4; nt++) {
        const int gcol = n0 + warp_n + nt * 8 + qc;
        if (gcol < 256) {
            // h output: fp16
#pragma unroll
            for (int mt = 0; mt < 4; mt++) {
                const int r0 = m0 + warp_m + mt * 16 + qr;
                if (r0 < M) {
                    __half2 v = __floats2half2_rn(d[mt][nt][0], d[mt][nt][1]);
                    *(__half2*)&Ch16[(size_t)r0 * HC + gcol] = v;
                }
                if (r0 + 8 < M) {
                    __half2 v = __floats2half2_rn(d[mt][nt][2], d[mt][nt][3]);
                    *(__half2*)&Ch16[(size_t)(r0 + 8) * HC + gcol] = v;
                }
            }
        } else {
            const int col = gcol - 256;
            const float bv0 = bias1[col] + bias2[col];
            const float bv1 = bias1[col + 1] + bias2[col + 1];
#pragma unroll
            for (int mt = 0; mt < 4; mt++) {
                const int r0 = m0 + warp_m + mt * 16 + qr;
                if (r0 < M) {
                    float2 v = make_float2(d[mt][nt][0] + bv0, d[mt][nt][1] + bv1);
                    *(float2*)&Cacc[(size_t)r0 * HC + col] = v;
                }
                if (r0 + 8 < M) {
                    float2 v = make_float2(d[mt][nt][2] + bv0, d[mt][nt][3] + bv1);
                    *(float2*)&Cacc[(size_t)(r0 + 8) * HC + col] = v;
                }
            }
        }
    }
}

// ------------------------- CSR build ---------------------------------------
__global__ void hist_kernel(const int* __restrict__ ei, int* __restrict__ deg,
                            int nE, int nTot) {
    const int e = blockIdx.x * blockDim.x + threadIdx.x;
    if (e >= nTot) return;
    const int d = (e < nE) ? ei[nE + e] : (e - nE);
    atomicAdd(&deg[d], 1);
}

__global__ void scan1_kernel(const int* __restrict__ deg, int* __restrict__ bsum,
                             int n) {
    __shared__ int sh[256];
    const int b0 = blockIdx.x * SCAN_BLK;
    const int t = threadIdx.x;
    int s = 0;
    if (b0 + t < n)       s += deg[b0 + t];
    if (b0 + 256 + t < n) s += deg[b0 + 256 + t];
    sh[t] = s;
    __syncthreads();
    for (int off = 128; off > 0; off >>= 1) {
        if (t < off) sh[t] += sh[t + off];
        __syncthreads();
    }
    if (t == 0) bsum[blockIdx.x] = sh[0];
}

__global__ void scan2_kernel(int* __restrict__ bsum, int nb) {
    __shared__ int sh[256];
    const int t = threadIdx.x;
    sh[t] = (t < nb) ? bsum[t] : 0;
    __syncthreads();
    for (int off = 1; off < 256; off <<= 1) {
        const int v = (t >= off) ? sh[t - off] : 0;
        __syncthreads();
        sh[t] += v;
        __syncthreads();
    }
    if (t < nb) bsum[t] = (t == 0) ? 0 : sh[t - 1];
}

__global__ void scan3_kernel(const int* __restrict__ deg,
                             const int* __restrict__ bsum,
                             int* __restrict__ rp, int* __restrict__ cur,
                             int n) {
    __shared__ int sh[SCAN_BLK];
    const int b0 = blockIdx.x * SCAN_BLK;
    const int t = threadIdx.x;
    const int v0 = (b0 + t < n) ? deg[b0 + t] : 0;
    const int v1 = (b0 + 256 + t < n) ? deg[b0 + 256 + t] : 0;
    sh[t] = v0;
    sh[256 + t] = v1;
    __syncthreads();
    for (int off = 1; off < SCAN_BLK; off <<= 1) {
        const int a0 = (t >= off) ? sh[t - off] : 0;
        const int a1 = (t + 256 >= off) ? sh[t + 256 - off] : 0;
        __syncthreads();
        sh[t] += a0;
        sh[256 + t] += a1;
        __syncthreads();
    }
    const int base = bsum[blockIdx.x];
    if (b0 + t < n) {
        const int ex = base + sh[t] - v0;
        rp[b0 + t] = ex;
        cur[b0 + t] = ex;
    }
    if (b0 + 256 + t < n) {
        const int ex = base + sh[256 + t] - v1;
        rp[b0 + 256 + t] = ex;
        cur[b0 + 256 + t] = ex;
    }
    if (blockIdx.x == gridDim.x - 1 && t == 0) rp[n] = base + sh[SCAN_BLK - 1];
}

__global__ void scatter_kernel(const int* __restrict__ ei, int* __restrict__ cur,
                               int* __restrict__ csr, int nE, int nTot) {
    const int e = blockIdx.x * blockDim.x + threadIdx.x;
    if (e >= nTot) return;
    int s, d;
    if (e < nE) { s = ei[e]; d = ei[nE + e]; }
    else        { s = d = e - nE; }
    const int pos = atomicAdd(&cur[d], 1);
    csr[pos] = s;
}

// ------------------------- s/d per node (fp16 h) ----------------------------
__global__ void compute_sd_kernel(const __half* __restrict__ gh,
                                  const float* __restrict__ a_src,
                                  const float* __restrict__ a_dst,
                                  float* __restrict__ gs, float* __restrict__ gd,
                                  int n_nodes) {
    const int warp = (blockIdx.x * blockDim.x + threadIdx.x) >> 5;
    const int lane = threadIdx.x & 31;
    if (warp >= n_nodes) return;
    const __half* hr = gh + (size_t)warp * HC;
#pragma unroll
    for (int h = 0; h < 4; h++) {
        const float h1 = __half2float(hr[h * 64 + lane]);
        const float h2 = __half2float(hr[h * 64 + 32 + lane]);
        float s = h1 * a_src[h * 64 + lane] + h2 * a_src[h * 64 + 32 + lane];
        float d = h1 * a_dst[h * 64 + lane] + h2 * a_dst[h * 64 + 32 + lane];
#pragma unroll
        for (int off = 16; off > 0; off >>= 1) {
            s += __shfl_down_sync(0xFFFFFFFFu, s, off);
            d += __shfl_down_sync(0xFFFFFFFFu, d, off);
        }
        if (lane == 0) {
            gs[warp * 4 + h] = s;
            gd[warp * 4 + h] = d;
        }
    }
}

// ------------------------- fused softmax + aggregate + skip + ELU ----------
// pass 3 gathers fp16 h: 16B per lane per edge (was 32B)
__global__ __launch_bounds__(256)
void node_agg_kernel(const int* __restrict__ rp, const int* __restrict__ csr,
                     const float* __restrict__ gs, const float* __restrict__ gd,
                     const __half* __restrict__ gh, const float* __restrict__ gskip,
                     float* __restrict__ xout,
                     __half* __restrict__ x16,
                     int nN) {
    const int v = (blockIdx.x * blockDim.x + threadIdx.x) >> 5;
    const int lane = threadIdx.x & 31;
    if (v >= nN) return;

    const int b = rp[v];
    const int e = rp[v + 1];
    const float4 dv = ((const float4*)gd)[v];

    float m0 = -1e30f, m1 = -1e30f, m2 = -1e30f, m3 = -1e30f;
    for (int i = b + lane; i < e; i += 32) {
        const float4 sv = ((const float4*)gs)[csr[i]];
        m0 = fmaxf(m0, lrelu(sv.x + dv.x));
        m1 = fmaxf(m1, lrelu(sv.y + dv.y));
        m2 = fmaxf(m2, lrelu(sv.z + dv.z));
        m3 = fmaxf(m3, lrelu(sv.w + dv.w));
    }
#pragma unroll
    for (int off = 16; off > 0; off >>= 1) {
        m0 = fmaxf(m0, __shfl_xor_sync(0xFFFFFFFFu, m0, off));
        m1 = fmaxf(m1, __shfl_xor_sync(0xFFFFFFFFu, m1, off));
        m2 = fmaxf(m2, __shfl_xor_sync(0xFFFFFFFFu, m2, off));
        m3 = fmaxf(m3, __shfl_xor_sync(0xFFFFFFFFu, m3, off));
    }

    float n0 = 0.f, n1 = 0.f, n2 = 0.f, n3 = 0.f;
    for (int i = b + lane; i < e; i += 32) {
        const float4 sv = ((const float4*)gs)[csr[i]];
        n0 += expf(lrelu(sv.x + dv.x) - m0);
        n1 += expf(lrelu(sv.y + dv.y) - m1);
        n2 += expf(lrelu(sv.z + dv.z) - m2);
        n3 += expf(lrelu(sv.w + dv.w) - m3);
    }
#pragma unroll
    for (int off = 16; off > 0; off >>= 1) {
        n0 += __shfl_xor_sync(0xFFFFFFFFu, n0, off);
        n1 += __shfl_xor_sync(0xFFFFFFFFu, n1, off);
        n2 += __shfl_xor_sync(0xFFFFFFFFu, n2, off);
        n3 += __shfl_xor_sync(0xFFFFFFFFu, n3, off);
    }

    const int h = lane >> 3;
    const float dvh  = (h < 2) ? (h == 0 ? dv.x : dv.y) : (h == 2 ? dv.z : dv.w);
    const float mh   = (h < 2) ? (h == 0 ? m0 : m1) : (h == 2 ? m2 : m3);
    const float dnh  = (h < 2) ? (h == 0 ? n0 : n1) : (h == 2 ? n2 : n3);
    const float invh = 1.f / (dnh + 1e-16f);

    // pass 3: lane owns channels [lane*8, lane*8+8) -> 8 halves = 1 uint4
    float4 a0 = make_float4(0.f, 0.f, 0.f, 0.f);
    float4 a1 = make_float4(0.f, 0.f, 0.f, 0.f);
#pragma unroll 2
    for (int i = b; i < e; i++) {
        const int s = csr[i];
        const float sval = gs[s * 4 + h];
        const float al = expf(lrelu(sval + dvh) - mh) * invh;
        const uint4 hv = *(const uint4*)(gh + (size_t)s * HC + lane * 8);
        const float2 f0 = __half22float2(*(const __half2*)&hv.x);
        const float2 f1 = __half22float2(*(const __half2*)&hv.y);
        const float2 f2 = __half22float2(*(const __half2*)&hv.z);
        const float2 f3 = __half22float2(*(const __half2*)&hv.w);
        a0.x = fmaf(f0.x, al, a0.x);  a0.y = fmaf(f0.y, al, a0.y);
        a0.z = fmaf(f1.x, al, a0.z);  a0.w = fmaf(f1.y, al, a0.w);
        a1.x = fmaf(f2.x, al, a1.x);  a1.y = fmaf(f2.y, al, a1.y);
        a1.z = fmaf(f3.x, al, a1.z);  a1.w = fmaf(f3.y, al, a1.w);
    }

    const float4* sp = (const float4*)(gskip + (size_t)v * HC) + lane * 2;
    const float4 s0 = sp[0];
    const float4 s1 = sp[1];
    float4 o0, o1;
    o0.x = a0.x + s0.x;  o0.y = a0.y + s0.y;  o0.z = a0.z + s0.z;  o0.w = a0.w + s0.w;
    o1.x = a1.x + s1.x;  o1.y = a1.y + s1.y;  o1.z = a1.z + s1.z;  o1.w = a1.w + s1.w;
    o0.x = o0.x > 0.f ? o0.x : expm1f(o0.x);
    o0.y = o0.y > 0.f ? o0.y : expm1f(o0.y);
    o0.z = o0.z > 0.f ? o0.z : expm1f(o0.z);
    o0.w = o0.w > 0.f ? o0.w : expm1f(o0.w);
    o1.x = o1.x > 0.f ? o1.x : expm1f(o1.x);
    o1.y = o1.y > 0.f ? o1.y : expm1f(o1.y);
    o1.z = o1.z > 0.f ? o1.z : expm1f(o1.z);
    o1.w = o1.w > 0.f ? o1.w : expm1f(o1.w);
    float4* op = (float4*)(xout + (size_t)v * HC) + lane * 2;
    op[0] = o0;
    op[1] = o1;

    if (x16) {
        __half2 p0 = __floats2half2_rn(o0.x, o0.y);
        __half2 p1 = __floats2half2_rn(o0.z, o0.w);
        __half2 p2 = __floats2half2_rn(o1.x, o1.y);
        __half2 p3 = __floats2half2_rn(o1.z, o1.w);
        uint4 u = make_uint4(*(uint32_t*)&p0, *(uint32_t*)&p1,
                             *(uint32_t*)&p2, *(uint32_t*)&p3);
        *(uint4*)(x16 + (size_t)v * HC + lane * 8) = u;
    }
}

// ---------------------------------------------------------------------------
extern "C" void kernel_launch(void* const* d_in, const int* in_sizes, int n_in,
                              void* d_out, int out_size) {
    const float* x0 = (const float*)d_in[0];
    const int* ei = (const int*)d_in[1];
    const int nE = in_sizes[1] / 2;
    const int nN = NNODES;
    const int nTot = nE + nN;

    const float* W[3]    = {(const float*)d_in[2],  (const float*)d_in[8],  (const float*)d_in[14]};
    const float* ASRC[3] = {(const float*)d_in[3],  (const float*)d_in[9],  (const float*)d_in[15]};
    const float* ADST[3] = {(const float*)d_in[4],  (const float*)d_in[10], (const float*)d_in[16]};
    const float* BB[3]   = {(const float*)d_in[5],  (const float*)d_in[11], (const float*)d_in[17]};
    const float* SW[3]   = {(const float*)d_in[6],  (const float*)d_in[12], (const float*)d_in[18]};
    const float* SB[3]   = {(const float*)d_in[7],  (const float*)d_in[13], (const float*)d_in[19]};
    const int FIN[3] = {128, HC, HC};

    float *pacc, *px, *ps, *pd;
    int *pdeg, *pcur, *prp, *pcsr, *pbsum;
    __half *pbh, *pbl, *pa16, *ph16;
    cudaGetSymbolAddress((void**)&ph16, g_h16);
    cudaGetSymbolAddress((void**)&pacc, g_acc);
    cudaGetSymbolAddress((void**)&px,   g_x);
    cudaGetSymbolAddress((void**)&ps,   g_s);
    cudaGetSymbolAddress((void**)&pd,   g_d);
    cudaGetSymbolAddress((void**)&pdeg, g_deg);
    cudaGetSymbolAddress((void**)&pcur, g_cur);
    cudaGetSymbolAddress((void**)&prp,  g_rp);
    cudaGetSymbolAddress((void**)&pcsr, g_csr);
    cudaGetSymbolAddress((void**)&pbsum,g_bsum);
    cudaGetSymbolAddress((void**)&pbh,  g_bh);
    cudaGetSymbolAddress((void**)&pbl,  g_bl);
    cudaGetSymbolAddress((void**)&pa16, g_a16);

    cudaFuncSetAttribute(gemm_mma_kernel,
                         cudaFuncAttributeMaxDynamicSharedMemorySize, GEMM_SMEM);

    const dim3 gemmGrid(4, (nN + 127) / 128);
    const int eBlocks   = (nTot + 255) / 256;
    const int sdBlocks  = (nN * 32 + 255) / 256;
    const int aggBlocks = (nN * 32 + 255) / 256;
    const int scanBlocks = (nN + SCAN_BLK - 1) / SCAN_BLK;

    prep_kernel<<<1280, 256>>>(W[0], SW[0], W[1], SW[1], W[2], SW[2],
                               pbh, pbl, pdeg);
    conv_a_kernel<<<(nN * 128 + 255) / 256, 256>>>(x0, pa16, nN * 128);
    hist_kernel<<<eBlocks, 256>>>(ei, pdeg, nE, nTot);

    // layer-1 GEMM (profiled by ncu)
    gemm_mma_kernel<<<gemmGrid, 256, GEMM_SMEM>>>(pa16, pbh, pbl, ph16, pacc,
                                                  BB[0], SB[0], nN, 128);

    scan1_kernel<<<scanBlocks, 256>>>(pdeg, pbsum, nN);
    scan2_kernel<<<1, 256>>>(pbsum, scanBlocks);
    scan3_kernel<<<scanBlocks, 256>>>(pdeg, pbsum, prp, pcur, nN);
    scatter_kernel<<<eBlocks, 256>>>(ei, pcur, pcsr, nE, nTot);

    for (int l = 0; l < 3; l++) {
        if (l > 0) {
            __half* bh = pbh + (size_t)l * 131072;
            __half* bl = pbl + (size_t)l * 131072;
            gemm_mma_kernel<<<gemmGrid, 256, GEMM_SMEM>>>(pa16, bh, bl, ph16, pacc,
                                                          BB[l], SB[l], nN, FIN[l]);
        }
        compute_sd_kernel<<<sdBlocks, 256>>>(ph16, ASRC[l], ADST[l], ps, pd, nN);
        float* xout = (l == 2) ? (float*)d_out : px;
        __half* x16 = (l == 2) ? nullptr : pa16;
        node_agg_kernel<<<aggBlocks, 256>>>(prp, pcsr, ps, pd, ph16, pacc,
                                            xout, x16, nN);
    }
}

// round 13
// speedup vs baseline: 1.5812x; 1.0326x over previous
#include <cuda_runtime.h>
#include <cuda_fp16.h>
#include <cstdint>

// ---------------------------------------------------------------------------
// GATEncoder: 3 layers of (GATConv + linear skip + ELU)
// N=50000, E=800000 (+N self loops), IN=128, H=4, C=64, HC=256
// Round 13: ldmatrix fragment loads + 3-stage cp.async pipeline (1 barrier
//           per chunk) + dead fp32 activation stores removed (layers 0-1).
// ---------------------------------------------------------------------------

#define NNODES 50000
#define NEDGES 800000
#define ETOT   (NEDGES + NNODES)
#define HC     256
#define SCAN_BLK 512
#define SSTR 40
#define STG  (128 * SSTR)              // halves per matrix per stage
#define STAGE_B (3 * STG * 2)          // bytes per stage: A, Bh, Bl
#define GEMM_SMEM (3 * STAGE_B)        // 3 stages

// ------------------------- static device scratch ---------------------------
__device__ __half g_h16[(size_t)NNODES * HC];
__device__ float g_acc [(size_t)NNODES * HC];
__device__ float g_s   [(size_t)NNODES * 4];
__device__ float g_d   [(size_t)NNODES * 4];
__device__ int   g_deg [NNODES];
__device__ int   g_cur [NNODES];
__device__ int   g_rp  [NNODES + 1];
__device__ int   g_csr [ETOT];
__device__ int   g_bsum[256];
__device__ __half g_a16[(size_t)NNODES * HC];
__device__ __half g_bh [3][131072];
__device__ __half g_bl [3][131072];

// ------------------------- helpers ----------------------------------------
__device__ __forceinline__ float lrelu(float v) { return v > 0.f ? v : 0.2f * v; }

__device__ __forceinline__ void mma16816(float* d, const uint32_t* a,
                                         uint32_t b0, uint32_t b1) {
    asm volatile(
        "mma.sync.aligned.m16n8k16.row.col.f32.f16.f16.f32 "
        "{%0,%1,%2,%3}, {%4,%5,%6,%7}, {%8,%9}, {%0,%1,%2,%3};"
        : "+f"(d[0]), "+f"(d[1]), "+f"(d[2]), "+f"(d[3])
        : "r"(a[0]), "r"(a[1]), "r"(a[2]), "r"(a[3]), "r"(b0), "r"(b1));
}

__device__ __forceinline__ void cp16(uint32_t dst, const __half* src, int srcsz) {
    asm volatile("cp.async.cg.shared.global [%0], [%1], 16, %2;"
                 :: "r"(dst), "l"(src), "r"(srcsz));
}

__device__ __forceinline__ void ldm_x4(uint32_t* r, uint32_t addr) {
    asm volatile("ldmatrix.sync.aligned.m8n8.x4.shared.b16 {%0,%1,%2,%3}, [%4];"
                 : "=r"(r[0]), "=r"(r[1]), "=r"(r[2]), "=r"(r[3]) : "r"(addr));
}
__device__ __forceinline__ void ldm_x2(uint32_t& r0, uint32_t& r1, uint32_t addr) {
    asm volatile("ldmatrix.sync.aligned.m8n8.x2.shared.b16 {%0,%1}, [%2];"
                 : "=r"(r0), "=r"(r1) : "r"(addr));
}

// ------------------------- prep ---------------------------------------------
__global__ void prep_kernel(const float* __restrict__ W1, const float* __restrict__ SW1,
                            const float* __restrict__ W2, const float* __restrict__ SW2,
                            const float* __restrict__ W3, const float* __restrict__ SW3,
                            __half* __restrict__ bh, __half* __restrict__ bl,
                            int* __restrict__ deg) {
    const int idx = blockIdx.x * blockDim.x + threadIdx.x;
    if (idx < NNODES) deg[idx] = 0;
    if (idx >= 327680) return;
    int l, which, mi, K;
    const float* src;
    if (idx < 65536)       { l = 0; K = 128; const int r = idx;          which = r >> 15; mi = r & 32767; src = which ? SW1 : W1; }
    else if (idx < 196608) { l = 1; K = 256; const int r = idx - 65536;  which = r >> 16; mi = r & 65535; src = which ? SW2 : W2; }
    else                   { l = 2; K = 256; const int r = idx - 196608; which = r >> 16; mi = r & 65535; src = which ? SW3 : W3; }
    const int k = mi >> 8;
    const int n = mi & 255;
    const float v = src[mi];
    const __half h = __float2half_rn(v);
    const size_t off = (size_t)l * 131072 + (size_t)(which * 256 + n) * K + k;
    bh[off] = h;
    bl[off] = __float2half_rn(v - __half2float(h));
}

// ------------------------- conv_a -------------------------------------------
__global__ void conv_a_kernel(const float* __restrict__ X,
                              __half* __restrict__ a16, int total) {
    const int idx = blockIdx.x * blockDim.x + threadIdx.x;
    if (idx >= total) return;
    a16[idx] = __float2half_rn(X[idx]);
}

// ------------------------- fused dual GEMM: 3-stage pipe + ldmatrix --------
__global__ __launch_bounds__(256, 2)
void gemm_mma_kernel(const __half* __restrict__ A,
                     const __half* __restrict__ Bh,
                     const __half* __restrict__ Bl,
                     __half* __restrict__ Ch16,
                     float* __restrict__ Cacc,
                     const float* __restrict__ bias1,
                     const float* __restrict__ bias2,
                     int M, int K) {
    extern __shared__ __half smem[];

    const int tid = threadIdx.x;
    const int wid = tid >> 5;
    const int lane = tid & 31;
    const int qr = lane >> 2;
    const int qc = (lane & 3) * 2;
    const int warp_m = (wid >> 2) * 64;
    const int warp_n = (wid & 3) * 32;
    const int m0 = blockIdx.y * 128;
    const int n0 = blockIdx.x * 128;

    float d[4][4][4];
#pragma unroll
    for (int mt = 0; mt < 4; mt++)
#pragma unroll
        for (int nt = 0; nt < 4; nt++)
#pragma unroll
            for (int r = 0; r < 4; r++) d[mt][nt][r] = 0.f;

    // loaders
    const int ar = tid >> 1;
    const int akh = (tid & 1) * 16;
    const int aguard = (m0 + ar < M) ? 16 : 0;
    const size_t abase = (size_t)(m0 + ar) * K + akh;
    const size_t bbase = (size_t)(n0 + ar) * K + akh;

    const uint32_t sbase = (uint32_t)__cvta_generic_to_shared(smem);
    const uint32_t stOfs = (uint32_t)(ar * SSTR + akh) * 2;   // bytes in matrix

    // ldmatrix per-lane fragment offsets (bytes within matrix)
    uint32_t aofs[4], bofs[4];
#pragma unroll
    for (int mt = 0; mt < 4; mt++)
        aofs[mt] = (uint32_t)((warp_m + mt * 16 + (lane & 15)) * SSTR +
                              ((lane >> 4) << 3)) * 2;
#pragma unroll
    for (int nt = 0; nt < 4; nt++)
        bofs[nt] = (uint32_t)((warp_n + nt * 8 + (lane & 7)) * SSTR +
                              (((lane >> 3) & 1) << 3)) * 2;

    const int nch = K >> 5;

    // prologue: chunks 0,1 into stages 0,1
#pragma unroll
    for (int p = 0; p < 2; p++) {
        const uint32_t st = sbase + p * STAGE_B;
        const int kp = p << 5;
        cp16(st + stOfs,                  A + abase + kp,      aguard);
        cp16(st + stOfs + 16,             A + abase + kp + 8,  aguard);
        cp16(st + STG * 2 + stOfs,        Bh + bbase + kp,     16);
        cp16(st + STG * 2 + stOfs + 16,   Bh + bbase + kp + 8, 16);
        cp16(st + 2 * STG * 2 + stOfs,    Bl + bbase + kp,     16);
        cp16(st + 2 * STG * 2 + stOfs + 16, Bl + bbase + kp + 8, 16);
        asm volatile("cp.async.commit_group;");
    }

    int stage = 0;
    for (int ch = 0; ch < nch; ch++) {
        if (ch + 1 < nch) asm volatile("cp.async.wait_group 1;");
        else              asm volatile("cp.async.wait_group 0;");
        __syncthreads();

        // issue chunk ch+2 into stage (ch+2)%3 (its previous user, chunk
        // ch-1, is fully consumed: all warps passed the barrier above)
        if (ch + 2 < nch) {
            int s2 = stage + 2; if (s2 >= 3) s2 -= 3;
            const uint32_t st = sbase + s2 * STAGE_B;
            const int kp = (ch + 2) << 5;
            cp16(st + stOfs,                  A + abase + kp,      aguard);
            cp16(st + stOfs + 16,             A + abase + kp + 8,  aguard);
            cp16(st + STG * 2 + stOfs,        Bh + bbase + kp,     16);
            cp16(st + STG * 2 + stOfs + 16,   Bh + bbase + kp + 8, 16);
            cp16(st + 2 * STG * 2 + stOfs,    Bl + bbase + kp,     16);
            cp16(st + 2 * STG * 2 + stOfs + 16, Bl + bbase + kp + 8, 16);
            asm volatile("cp.async.commit_group;");
        }

        const uint32_t stA  = sbase + stage * STAGE_B;
        const uint32_t stBh = stA + STG * 2;
        const uint32_t stBl = stA + 2 * STG * 2;

#pragma unroll
        for (int ks = 0; ks < 2; ks++) {
            const uint32_t kb = ks * 32;   // 16 halves = 32 bytes
            uint32_t ah[4][4];
#pragma unroll
            for (int mt = 0; mt < 4; mt++)
                ldm_x4(ah[mt], stA + aofs[mt] + kb);
#pragma unroll
            for (int nt = 0; nt < 4; nt++) {
                uint32_t bh0, bh1, bl0, bl1;
                ldm_x2(bh0, bh1, stBh + bofs[nt] + kb);
                ldm_x2(bl0, bl1, stBl + bofs[nt] + kb);
#pragma unroll
                for (int mt = 0; mt < 4; mt++) {
                    mma16816(d[mt][nt], ah[mt], bh0, bh1);
                    mma16816(d[mt][nt], ah[mt], bl0, bl1);
                }
            }
        }
        if (++stage == 3) stage = 0;
    }

#pragma unroll
    for (int nt = 0; nt < 4; nt++) {
        const int gcol = n0 + warp_n + nt * 8 + qc;
        if (gcol < 256) {
#pragma unroll
            for (int mt = 0; mt < 4; mt++) {
                const int r0 = m0 + warp_m + mt * 16 + qr;
                if (r0 < M) {
                    __half2 v = __floats2half2_rn(d[mt][nt][0], d[mt][nt][1]);
                    *(__half2*)&Ch16[(size_t)r0 * HC + gcol] = v;
                }
                if (r0 + 8 < M) {
                    __half2 v = __floats2half2_rn(d[mt][nt][2], d[mt][nt][3]);
                    *(__half2*)&Ch16[(size_t)(r0 + 8) * HC + gcol] = v;
                }
            }
        } else {
            const int col = gcol - 256;
            const float bv0 = bias1[col] + bias2[col];
            const float bv1 = bias1[col + 1] + bias2[col + 1];
#pragma unroll
            for (int mt = 0; mt < 4; mt++) {
                const int r0 = m0 + warp_m + mt * 16 + qr;
                if (r0 < M) {
                    float2 v = make_float2(d[mt][nt][0] + bv0, d[mt][nt][1] + bv1);
                    *(float2*)&Cacc[(size_t)r0 * HC + col] = v;
                }
                if (r0 + 8 < M) {
                    float2 v = make_float2(d[mt][nt][2] + bv0, d[mt][nt][3] + bv1);
                    *(float2*)&Cacc[(size_t)(r0 + 8) * HC + col] = v;
                }
            }
        }
    }
}

// ------------------------- CSR build ---------------------------------------
__global__ void hist_kernel(const int* __restrict__ ei, int* __restrict__ deg,
                            int nE, int nTot) {
    const int e = blockIdx.x * blockDim.x + threadIdx.x;
    if (e >= nTot) return;
    const int d = (e < nE) ? ei[nE + e] : (e - nE);
    atomicAdd(&deg[d], 1);
}

__global__ void scan1_kernel(const int* __restrict__ deg, int* __restrict__ bsum,
                             int n) {
    __shared__ int sh[256];
    const int b0 = blockIdx.x * SCAN_BLK;
    const int t = threadIdx.x;
    int s = 0;
    if (b0 + t < n)       s += deg[b0 + t];
    if (b0 + 256 + t < n) s += deg[b0 + 256 + t];
    sh[t] = s;
    __syncthreads();
    for (int off = 128; off > 0; off >>= 1) {
        if (t < off) sh[t] += sh[t + off];
        __syncthreads();
    }
    if (t == 0) bsum[blockIdx.x] = sh[0];
}

__global__ void scan2_kernel(int* __restrict__ bsum, int nb) {
    __shared__ int sh[256];
    const int t = threadIdx.x;
    sh[t] = (t < nb) ? bsum[t] : 0;
    __syncthreads();
    for (int off = 1; off < 256; off <<= 1) {
        const int v = (t >= off) ? sh[t - off] : 0;
        __syncthreads();
        sh[t] += v;
        __syncthreads();
    }
    if (t < nb) bsum[t] = (t == 0) ? 0 : sh[t - 1];
}

__global__ void scan3_kernel(const int* __restrict__ deg,
                             const int* __restrict__ bsum,
                             int* __restrict__ rp, int* __restrict__ cur,
                             int n) {
    __shared__ int sh[SCAN_BLK];
    const int b0 = blockIdx.x * SCAN_BLK;
    const int t = threadIdx.x;
    const int v0 = (b0 + t < n) ? deg[b0 + t] : 0;
    const int v1 = (b0 + 256 + t < n) ? deg[b0 + 256 + t] : 0;
    sh[t] = v0;
    sh[256 + t] = v1;
    __syncthreads();
    for (int off = 1; off < SCAN_BLK; off <<= 1) {
        const int a0 = (t >= off) ? sh[t - off] : 0;
        const int a1 = (t + 256 >= off) ? sh[t + 256 - off] : 0;
        __syncthreads();
        sh[t] += a0;
        sh[256 + t] += a1;
        __syncthreads();
    }
    const int base = bsum[blockIdx.x];
    if (b0 + t < n) {
        const int ex = base + sh[t] - v0;
        rp[b0 + t] = ex;
        cur[b0 + t] = ex;
    }
    if (b0 + 256 + t < n) {
        const int ex = base + sh[256 + t] - v1;
        rp[b0 + 256 + t] = ex;
        cur[b0 + 256 + t] = ex;
    }
    if (blockIdx.x == gridDim.x - 1 && t == 0) rp[n] = base + sh[SCAN_BLK - 1];
}

__global__ void scatter_kernel(const int* __restrict__ ei, int* __restrict__ cur,
                               int* __restrict__ csr, int nE, int nTot) {
    const int e = blockIdx.x * blockDim.x + threadIdx.x;
    if (e >= nTot) return;
    int s, d;
    if (e < nE) { s = ei[e]; d = ei[nE + e]; }
    else        { s = d = e - nE; }
    const int pos = atomicAdd(&cur[d], 1);
    csr[pos] = s;
}

// ------------------------- s/d per node (fp16 h) ----------------------------
__global__ void compute_sd_kernel(const __half* __restrict__ gh,
                                  const float* __restrict__ a_src,
                                  const float* __restrict__ a_dst,
                                  float* __restrict__ gs, float* __restrict__ gd,
                                  int n_nodes) {
    const int warp = (blockIdx.x * blockDim.x + threadIdx.x) >> 5;
    const int lane = threadIdx.x & 31;
    if (warp >= n_nodes) return;
    const __half* hr = gh + (size_t)warp * HC;
#pragma unroll
    for (int h = 0; h < 4; h++) {
        const float h1 = __half2float(hr[h * 64 + lane]);
        const float h2 = __half2float(hr[h * 64 + 32 + lane]);
        float s = h1 * a_src[h * 64 + lane] + h2 * a_src[h * 64 + 32 + lane];
        float d = h1 * a_dst[h * 64 + lane] + h2 * a_dst[h * 64 + 32 + lane];
#pragma unroll
        for (int off = 16; off > 0; off >>= 1) {
            s += __shfl_down_sync(0xFFFFFFFFu, s, off);
            d += __shfl_down_sync(0xFFFFFFFFu, d, off);
        }
        if (lane == 0) {
            gs[warp * 4 + h] = s;
            gd[warp * 4 + h] = d;
        }
    }
}

// ------------------------- fused softmax + aggregate + skip + ELU ----------
__global__ __launch_bounds__(256)
void node_agg_kernel(const int* __restrict__ rp, const int* __restrict__ csr,
                     const float* __restrict__ gs, const float* __restrict__ gd,
                     const __half* __restrict__ gh, const float* __restrict__ gskip,
                     float* __restrict__ xout,
                     __half* __restrict__ x16,
                     int nN) {
    const int v = (blockIdx.x * blockDim.x + threadIdx.x) >> 5;
    const int lane = threadIdx.x & 31;
    if (v >= nN) return;

    const int b = rp[v];
    const int e = rp[v + 1];
    const float4 dv = ((const float4*)gd)[v];

    float m0 = -1e30f, m1 = -1e30f, m2 = -1e30f, m3 = -1e30f;
    for (int i = b + lane; i < e; i += 32) {
        const float4 sv = ((const float4*)gs)[csr[i]];
        m0 = fmaxf(m0, lrelu(sv.x + dv.x));
        m1 = fmaxf(m1, lrelu(sv.y + dv.y));
        m2 = fmaxf(m2, lrelu(sv.z + dv.z));
        m3 = fmaxf(m3, lrelu(sv.w + dv.w));
    }
#pragma unroll
    for (int off = 16; off > 0; off >>= 1) {
        m0 = fmaxf(m0, __shfl_xor_sync(0xFFFFFFFFu, m0, off));
        m1 = fmaxf(m1, __shfl_xor_sync(0xFFFFFFFFu, m1, off));
        m2 = fmaxf(m2, __shfl_xor_sync(0xFFFFFFFFu, m2, off));
        m3 = fmaxf(m3, __shfl_xor_sync(0xFFFFFFFFu, m3, off));
    }

    float n0 = 0.f, n1 = 0.f, n2 = 0.f, n3 = 0.f;
    for (int i = b + lane; i < e; i += 32) {
        const float4 sv = ((const float4*)gs)[csr[i]];
        n0 += expf(lrelu(sv.x + dv.x) - m0);
        n1 += expf(lrelu(sv.y + dv.y) - m1);
        n2 += expf(lrelu(sv.z + dv.z) - m2);
        n3 += expf(lrelu(sv.w + dv.w) - m3);
    }
#pragma unroll
    for (int off = 16; off > 0; off >>= 1) {
        n0 += __shfl_xor_sync(0xFFFFFFFFu, n0, off);
        n1 += __shfl_xor_sync(0xFFFFFFFFu, n1, off);
        n2 += __shfl_xor_sync(0xFFFFFFFFu, n2, off);
        n3 += __shfl_xor_sync(0xFFFFFFFFu, n3, off);
    }

    const int h = lane >> 3;
    const float dvh  = (h < 2) ? (h == 0 ? dv.x : dv.y) : (h == 2 ? dv.z : dv.w);
    const float mh   = (h < 2) ? (h == 0 ? m0 : m1) : (h == 2 ? m2 : m3);
    const float dnh  = (h < 2) ? (h == 0 ? n0 : n1) : (h == 2 ? n2 : n3);
    const float invh = 1.f / (dnh + 1e-16f);

    float4 a0 = make_float4(0.f, 0.f, 0.f, 0.f);
    float4 a1 = make_float4(0.f, 0.f, 0.f, 0.f);
#pragma unroll 2
    for (int i = b; i < e; i++) {
        const int s = csr[i];
        const float sval = gs[s * 4 + h];
        const float al = expf(lrelu(sval + dvh) - mh) * invh;
        const uint4 hv = *(const uint4*)(gh + (size_t)s * HC + lane * 8);
        const float2 f0 = __half22float2(*(const __half2*)&hv.x);
        const float2 f1 = __half22float2(*(const __half2*)&hv.y);
        const float2 f2 = __half22float2(*(const __half2*)&hv.z);
        const float2 f3 = __half22float2(*(const __half2*)&hv.w);
        a0.x = fmaf(f0.x, al, a0.x);  a0.y = fmaf(f0.y, al, a0.y);
        a0.z = fmaf(f1.x, al, a0.z);  a0.w = fmaf(f1.y, al, a0.w);
        a1.x = fmaf(f2.x, al, a1.x);  a1.y = fmaf(f2.y, al, a1.y);
        a1.z = fmaf(f3.x, al, a1.z);  a1.w = fmaf(f3.y, al, a1.w);
    }

    const float4* sp = (const float4*)(gskip + (size_t)v * HC) + lane * 2;
    const float4 s0 = sp[0];
    const float4 s1 = sp[1];
    float4 o0, o1;
    o0.x = a0.x + s0.x;  o0.y = a0.y + s0.y;  o0.z = a0.z + s0.z;  o0.w = a0.w + s0.w;
    o1.x = a1.x + s1.x;  o1.y = a1.y + s1.y;  o1.z = a1.z + s1.z;  o1.w = a1.w + s1.w;
    o0.x = o0.x > 0.f ? o0.x : expm1f(o0.x);
    o0.y = o0.y > 0.f ? o0.y : expm1f(o0.y);
    o0.z = o0.z > 0.f ? o0.z : expm1f(o0.z);
    o0.w = o0.w > 0.f ? o0.w : expm1f(o0.w);
    o1.x = o1.x > 0.f ? o1.x : expm1f(o1.x);
    o1.y = o1.y > 0.f ? o1.y : expm1f(o1.y);
    o1.z = o1.z > 0.f ? o1.z : expm1f(o1.z);
    o1.w = o1.w > 0.f ? o1.w : expm1f(o1.w);

    if (xout) {
        float4* op = (float4*)(xout + (size_t)v * HC) + lane * 2;
        op[0] = o0;
        op[1] = o1;
    }
    if (x16) {
        __half2 p0 = __floats2half2_rn(o0.x, o0.y);
        __half2 p1 = __floats2half2_rn(o0.z, o0.w);
        __half2 p2 = __floats2half2_rn(o1.x, o1.y);
        __half2 p3 = __floats2half2_rn(o1.z, o1.w);
        uint4 u = make_uint4(*(uint32_t*)&p0, *(uint32_t*)&p1,
                             *(uint32_t*)&p2, *(uint32_t*)&p3);
        *(uint4*)(x16 + (size_t)v * HC + lane * 8) = u;
    }
}

// ---------------------------------------------------------------------------
extern "C" void kernel_launch(void* const* d_in, const int* in_sizes, int n_in,
                              void* d_out, int out_size) {
    const float* x0 = (const float*)d_in[0];
    const int* ei = (const int*)d_in[1];
    const int nE = in_sizes[1] / 2;
    const int nN = NNODES;
    const int nTot = nE + nN;

    const float* W[3]    = {(const float*)d_in[2],  (const float*)d_in[8],  (const float*)d_in[14]};
    const float* ASRC[3] = {(const float*)d_in[3],  (const float*)d_in[9],  (const float*)d_in[15]};
    const float* ADST[3] = {(const float*)d_in[4],  (const float*)d_in[10], (const float*)d_in[16]};
    const float* BB[3]   = {(const float*)d_in[5],  (const float*)d_in[11], (const float*)d_in[17]};
    const float* SW[3]   = {(const float*)d_in[6],  (const float*)d_in[12], (const float*)d_in[18]};
    const float* SB[3]   = {(const float*)d_in[7],  (const float*)d_in[13], (const float*)d_in[19]};
    const int FIN[3] = {128, HC, HC};

    float *pacc, *ps, *pd;
    int *pdeg, *pcur, *prp, *pcsr, *pbsum;
    __half *pbh, *pbl, *pa16, *ph16;
    cudaGetSymbolAddress((void**)&ph16, g_h16);
    cudaGetSymbolAddress((void**)&pacc, g_acc);
    cudaGetSymbolAddress((void**)&ps,   g_s);
    cudaGetSymbolAddress((void**)&pd,   g_d);
    cudaGetSymbolAddress((void**)&pdeg, g_deg);
    cudaGetSymbolAddress((void**)&pcur, g_cur);
    cudaGetSymbolAddress((void**)&prp,  g_rp);
    cudaGetSymbolAddress((void**)&pcsr, g_csr);
    cudaGetSymbolAddress((void**)&pbsum,g_bsum);
    cudaGetSymbolAddress((void**)&pbh,  g_bh);
    cudaGetSymbolAddress((void**)&pbl,  g_bl);
    cudaGetSymbolAddress((void**)&pa16, g_a16);

    cudaFuncSetAttribute(gemm_mma_kernel,
                         cudaFuncAttributeMaxDynamicSharedMemorySize, GEMM_SMEM);

    const dim3 gemmGrid(4, (nN + 127) / 128);
    const int eBlocks   = (nTot + 255) / 256;
    const int sdBlocks  = (nN * 32 + 255) / 256;
    const int aggBlocks = (nN * 32 + 255) / 256;
    const int scanBlocks = (nN + SCAN_BLK - 1) / SCAN_BLK;

    prep_kernel<<<1280, 256>>>(W[0], SW[0], W[1], SW[1], W[2], SW[2],
                               pbh, pbl, pdeg);
    conv_a_kernel<<<(nN * 128 + 255) / 256, 256>>>(x0, pa16, nN * 128);
    hist_kernel<<<eBlocks, 256>>>(ei, pdeg, nE, nTot);

    // layer-1 GEMM (profiled by ncu)
    gemm_mma_kernel<<<gemmGrid, 256, GEMM_SMEM>>>(pa16, pbh, pbl, ph16, pacc,
                                                  BB[0], SB[0], nN, 128);

    scan1_kernel<<<scanBlocks, 256>>>(pdeg, pbsum, nN);
    scan2_kernel<<<1, 256>>>(pbsum, scanBlocks);
    scan3_kernel<<<scanBlocks, 256>>>(pdeg, pbsum, prp, pcur, nN);
    scatter_kernel<<<eBlocks, 256>>>(ei, pcur, pcsr, nE, nTot);

    for (int l = 0; l < 3; l++) {
        if (l > 0) {
            __half* bh = pbh + (size_t)l * 131072;
            __half* bl = pbl + (size_t)l * 131072;
            gemm_mma_kernel<<<gemmGrid, 256, GEMM_SMEM>>>(pa16, bh, bl, ph16, pacc,
                                                          BB[l], SB[l], nN, FIN[l]);
        }
        compute_sd_kernel<<<sdBlocks, 256>>>(ph16, ASRC[l], ADST[l], ps, pd, nN);
        float* xout = (l == 2) ? (float*)d_out : nullptr;   // fp32 dead for l<2
        __half* x16 = (l == 2) ? nullptr : pa16;
        node_agg_kernel<<<aggBlocks, 256>>>(prp, pcsr, ps, pd, ph16, pacc,
                                            xout, x16, nN);
    }
}